// round 14
// baseline (speedup 1.0000x reference)
#include <cuda_runtime.h>
#include <cuda_bf16.h>
#include <math.h>
#include <stdint.h>

// Problem constants
#define BB 2
#define LL 1024
#define DD 512
#define RR (BB * LL)          // 2048 rows
#define TPJ 16                // total planes (NS*PP)
#define PDIM 16               // positional planes
#define NCHAN 36              // 16 bank + 4 cross + 16 positional
#define CCH 64                // chunks along L
#define SCH 16                // chunk size
#define HG 256                // g1 hidden
#define NBLK 128              // scan grid (<=148 for single-wave residency)

#define PI_F 3.14159265358979323846f

// ===================== base-ISA tensor helpers =====================
__device__ __forceinline__ uint32_t smem_u32(const void* p) {
    uint32_t a;
    asm("{ .reg .u64 t; cvta.to.shared.u64 t, %1; cvt.u32.u64 %0, t; }" : "=r"(a) : "l"(p));
    return a;
}
__device__ __forceinline__ void ldsm_x4(uint32_t* r, uint32_t addr) {
    asm volatile("ldmatrix.sync.aligned.m8n8.x4.shared.b16 {%0,%1,%2,%3}, [%4];"
                 : "=r"(r[0]), "=r"(r[1]), "=r"(r[2]), "=r"(r[3]) : "r"(addr));
}
__device__ __forceinline__ void mma16816(float* d, const uint32_t* a, const uint32_t* b) {
    asm volatile("mma.sync.aligned.m16n8k16.row.col.f32.bf16.bf16.f32 "
                 "{%0,%1,%2,%3}, {%4,%5,%6,%7}, {%8,%9}, {%0,%1,%2,%3};"
                 : "+f"(d[0]), "+f"(d[1]), "+f"(d[2]), "+f"(d[3])
                 : "r"(a[0]), "r"(a[1]), "r"(a[2]), "r"(a[3]), "r"(b[0]), "r"(b[1]));
}
#define CP_ASYNC16(sm, gp) \
    asm volatile("cp.async.cg.shared.global [%0], [%1], 16;" :: "r"(sm), "l"(gp))
#define CP_COMMIT() asm volatile("cp.async.commit_group;" ::: "memory")
#define CP_WAIT1() asm volatile("cp.async.wait_group 1;" ::: "memory")
#define CP_WAIT0() asm volatile("cp.async.wait_group 0;" ::: "memory")

// ===================== device scratch =====================
__device__ float2 g_S[BB * CCH * NCHAN * DD];
__device__ float  g_V[RR * DD];
__device__ float  g_hpre[RR * HG];
__device__ float  g_wg[RR];
__device__ float  g_kph[RR * 40];
__device__ float  g_qph[RR * 40];
__device__ float  g_jk[RR * 8];
__device__ float  g_posph[LL * 32];
__device__ __nv_bfloat16 g_xh[RR * DD], g_xl[RR * DD];
__device__ __nv_bfloat16 g_ynh[RR * DD], g_ynl[RR * DD];
__device__ __nv_bfloat16 g_wvh[DD * DD], g_wvl[DD * DD];
__device__ __nv_bfloat16 g_woh[DD * DD], g_wol[DD * DD];
__device__ __nv_bfloat16 g_wgh[HG * DD], g_wgl[HG * DD];

// grid-barrier state (epoch monotonic across replays; count self-resets)
__device__ unsigned g_count = 0;
__device__ unsigned g_epoch = 0;

// ===================== side-stream infra (static init: pre-checkpoint) =====
__global__ void warm_kernel() {}
struct SideStreams {
    cudaStream_t s2;
    cudaEvent_t evFork, evConv, evH;
    SideStreams() {
        cudaStreamCreateWithFlags(&s2, cudaStreamNonBlocking);
        cudaEventCreateWithFlags(&evFork, cudaEventDisableTiming);
        cudaEventCreateWithFlags(&evConv, cudaEventDisableTiming);
        cudaEventCreateWithFlags(&evH, cudaEventDisableTiming);
        warm_kernel<<<1, 32, 0, s2>>>();
        cudaDeviceSynchronize();
    }
};
static SideStreams g_ss;

// ===================== weight transpose+split helper =====================
__device__ __forceinline__ void conv_w_tile(const float* W, __nv_bfloat16* Th,
                                            __nv_bfloat16* Tl, int N,
                                            int n0, int k0, int tid,
                                            float (*t)[33])
{
    int tx = tid & 31, ty = tid >> 5;   // 32 x 8
#pragma unroll
    for (int i = 0; i < 32; i += 8) t[ty + i][tx] = W[(k0 + ty + i) * N + n0 + tx];
    __syncthreads();
#pragma unroll
    for (int i = 0; i < 32; i += 8) {
        float v = t[tx][ty + i];
        __nv_bfloat16 h = __float2bfloat16_rn(v);
        Th[(n0 + ty + i) * DD + k0 + tx] = h;
        Tl[(n0 + ty + i) * DD + k0 + tx] = __float2bfloat16_rn(v - __bfloat162float(h));
    }
}

// ===================== fused: x split + v_w split + phases (one launch) ====
// grid 1600: [0,1024) x-split, [1024,1280) v_w tiles, [1280,1536) proj phases,
// [1536,1600) positional phases
__global__ __launch_bounds__(256) void convert_phase_kernel(
    const float* __restrict__ x, const float* __restrict__ vw,
    const float* __restrict__ keyp, const float* __restrict__ queryp,
    const float* __restrict__ setw, const float* __restrict__ freqs)
{
    int bx = blockIdx.x, tid = threadIdx.x;
    if (bx < 1024) {
        int i = bx * 256 + tid;
        float4 v = ((const float4*)x)[i];
        float f[4] = {v.x, v.y, v.z, v.w};
        __nv_bfloat16 h[4], l[4];
#pragma unroll
        for (int k = 0; k < 4; k++) {
            h[k] = __float2bfloat16_rn(f[k]);
            l[k] = __float2bfloat16_rn(f[k] - __bfloat162float(h[k]));
        }
        ((__nv_bfloat162*)g_xh)[2 * i]     = __nv_bfloat162(h[0], h[1]);
        ((__nv_bfloat162*)g_xh)[2 * i + 1] = __nv_bfloat162(h[2], h[3]);
        ((__nv_bfloat162*)g_xl)[2 * i]     = __nv_bfloat162(l[0], l[1]);
        ((__nv_bfloat162*)g_xl)[2 * i + 1] = __nv_bfloat162(l[2], l[3]);
        return;
    }
    if (bx < 1280) {
        __shared__ float t[32][33];
        int rem = bx - 1024;
        conv_w_tile(vw, g_wvh, g_wvl, DD, (rem & 15) * 32, (rem >> 4) * 32, tid, t);
        return;
    }
    if (bx >= 1536) {
        int i = (bx - 1536) * 256 + tid;
        int l = i >> 4, p = i & 15;
        float a = ((float)l * freqs[p]) * (2.0f * PI_F);
        float s, c;
        sincosf(a, &s, &c);
        g_posph[l * 32 + 2 * p] = c;
        g_posph[l * 32 + 2 * p + 1] = s;
        return;
    }
    // projection phases: 8 rows per block, one warp per row
    int row = (bx - 1280) * 8 + (tid >> 5);
    int lane = tid & 31;
    int t = lane & 15;
    const float* W = (lane < 16) ? keyp : queryp;
    const float* xr = x + row * DD;
    float acc = 0.f;
    for (int k = 0; k < DD; k++) acc += xr[k] * W[k * TPJ + t];
    float theta = tanhf(acc) * PI_F;

    float csum = theta;
    csum += __shfl_xor_sync(0xffffffffu, csum, 4);
    csum += __shfl_xor_sync(0xffffffffu, csum, 8);

    float w0 = setw[0], w1 = setw[1], w2 = setw[2], w3 = setw[3];
    float m = fmaxf(fmaxf(w0, w1), fmaxf(w2, w3));
    float e0 = expf(w0 - m), e1 = expf(w1 - m), e2 = expf(w2 - m), e3 = expf(w3 - m);
    float inv = 1.f / (e0 + e1 + e2 + e3);
    float wv[4] = {e0 * inv, e1 * inv, e2 * inv, e3 * inv};

    float s, c;
    sincosf(theta, &s, &c);
    if (lane < 16) {
        g_kph[row * 40 + 2 * t] = c;
        g_kph[row * 40 + 2 * t + 1] = s;
        if (t < 4) {
            float s2, c2;
            sincosf(csum, &s2, &c2);
            g_kph[row * 40 + 2 * (16 + t)] = c2;
            g_kph[row * 40 + 2 * (16 + t) + 1] = s2;
            g_jk[row * 8 + 2 * t] = c2;
            g_jk[row * 8 + 2 * t + 1] = s2;
        }
    } else {
        float wq = wv[t >> 2] * 0.2f;
        g_qph[row * 40 + 2 * t] = c * wq;
        g_qph[row * 40 + 2 * t + 1] = s * wq;
        if (t < 4) {
            float s2, c2;
            sincosf(csum, &s2, &c2);
            g_qph[row * 40 + 2 * (16 + t)] = c2 * 0.2f;
            g_qph[row * 40 + 2 * (16 + t) + 1] = s2 * 0.2f;
        }
    }
}

// convert out_w + g1_w (off critical path, s2)
__global__ __launch_bounds__(256) void convert_og_kernel(
    const float* __restrict__ ow, const float* __restrict__ g1w)
{
    __shared__ float t[32][33];
    int bx = blockIdx.x, tid = threadIdx.x;
    if (bx < 256) {
        conv_w_tile(ow, g_woh, g_wol, DD, (bx & 15) * 32, (bx >> 4) * 32, tid, t);
        return;
    }
    int rem = bx - 256;
    int n0 = (rem & 7) * 32, k0 = (rem >> 3) * 32;
    conv_w_tile(g1w, g_wgh, g_wgl, HG, n0, k0, tid, t);
}

// ===================== mma.sync GEMM (bf16 hi/lo split) =====================
#define ST_EL 15360
#define GM_SMEM_BYTES (2 * ST_EL * 2)

template <bool RESID>
__global__ void __launch_bounds__(256) gemm_mma_kernel(
    const __nv_bfloat16* __restrict__ Ah, const __nv_bfloat16* __restrict__ Al,
    const __nv_bfloat16* __restrict__ Bh, const __nv_bfloat16* __restrict__ Bl,
    const float* __restrict__ bias, const float* __restrict__ resid,
    float* __restrict__ C, int Ntot)
{
    extern __shared__ __nv_bfloat16 smem[];
    const int tid = threadIdx.x, lane = tid & 31, wid = tid >> 5;
    const int wm = (wid >> 1) * 32, wn = (wid & 1) * 32;
    const int bm = blockIdx.y * 128, bn = blockIdx.x * 64;
    const int K = 512;

    uint32_t sbase = smem_u32(smem);
    int arow = tid >> 2, aq = tid & 3;
    int brow = tid >> 2, bq = tid & 3;

    auto load_chunk = [&](int c, int s) {
        uint32_t st = sbase + s * ST_EL * 2;
        int k0 = c * 32;
#pragma unroll
        for (int i = 0; i < 2; i++) {
            int r = arow + i * 64;
            uint32_t so = st + (r * 40 + aq * 8) * 2;
            CP_ASYNC16(so, Ah + (bm + r) * K + k0 + aq * 8);
            CP_ASYNC16(so + 5120 * 2, Al + (bm + r) * K + k0 + aq * 8);
        }
        {
            uint32_t so = st + (10240 + brow * 40 + bq * 8) * 2;
            CP_ASYNC16(so, Bh + (bn + brow) * K + k0 + bq * 8);
            CP_ASYNC16(so + 2560 * 2, Bl + (bn + brow) * K + k0 + bq * 8);
        }
    };

    float acc[2][4][4];
#pragma unroll
    for (int mt = 0; mt < 2; mt++)
#pragma unroll
        for (int nt = 0; nt < 4; nt++)
#pragma unroll
            for (int e = 0; e < 4; e++) acc[mt][nt][e] = 0.f;

    load_chunk(0, 0);
    CP_COMMIT();

    int a_row = (lane & 7) + ((lane >> 3) & 1) * 8;
    int a_k16 = ((lane >> 4) & 1) * 16;
    int b_row = (lane & 7) + ((lane >> 4) & 1) * 8;
    int b_k16 = ((lane >> 3) & 1) * 16;

    for (int c = 0; c < 16; c++) {
        int s = c & 1;
        if (c + 1 < 16) { load_chunk(c + 1, s ^ 1); CP_COMMIT(); CP_WAIT1(); }
        else CP_WAIT0();
        __syncthreads();

        uint32_t st = sbase + s * ST_EL * 2;
#pragma unroll
        for (int ks = 0; ks < 2; ks++) {
            uint32_t aH[8], aL[8], bH[8], bL[8];
#pragma unroll
            for (int mt = 0; mt < 2; mt++) {
                int row = wm + mt * 16 + a_row;
                uint32_t ad = st + (row * 40) * 2 + ks * 32 + a_k16;
                ldsm_x4(aH + mt * 4, ad);
                ldsm_x4(aL + mt * 4, ad + 5120 * 2);
            }
#pragma unroll
            for (int np = 0; np < 2; np++) {
                int row = wn + np * 16 + b_row;
                uint32_t bd = st + (10240 + row * 40) * 2 + ks * 32 + b_k16;
                ldsm_x4(bH + np * 4, bd);
                ldsm_x4(bL + np * 4, bd + 2560 * 2);
            }
#pragma unroll
            for (int mt = 0; mt < 2; mt++)
#pragma unroll
                for (int nt = 0; nt < 4; nt++) {
                    uint32_t* bh = bH + (nt >> 1) * 4 + (nt & 1) * 2;
                    uint32_t* bl = bL + (nt >> 1) * 4 + (nt & 1) * 2;
                    mma16816(acc[mt][nt], aH + mt * 4, bh);
                    mma16816(acc[mt][nt], aH + mt * 4, bl);
                    mma16816(acc[mt][nt], aL + mt * 4, bh);
                }
        }
        __syncthreads();
    }

#pragma unroll
    for (int mt = 0; mt < 2; mt++)
#pragma unroll
        for (int nt = 0; nt < 4; nt++) {
            int col = bn + wn + nt * 8 + (lane & 3) * 2;
            float b0 = bias[col], b1 = bias[col + 1];
#pragma unroll
            for (int h = 0; h < 2; h++) {
                int row = bm + wm + mt * 16 + (lane >> 2) + h * 8;
                float2 o;
                o.x = acc[mt][nt][h * 2 + 0] + b0;
                o.y = acc[mt][nt][h * 2 + 1] + b1;
                if (RESID) {
                    float2 rr = *(const float2*)&resid[row * Ntot + col];
                    o.x += rr.x; o.y += rr.y;
                }
                *(float2*)&C[row * Ntot + col] = o;
            }
        }
}

// ===================== fused scan: chunk sums + wg + GRID BAR + prefix =====
__global__ __launch_bounds__(512) void scan_kernel(
    const float* __restrict__ rscale, const float* __restrict__ rthr,
    const float* __restrict__ sscale, const float* __restrict__ sbias)
{
    int bx = blockIdx.x;
    int b = bx >> 6, j = bx & 63, d = threadIdx.x;
    int lane = d & 31, wrp = d >> 5;
    int l0 = j * SCH;
    __shared__ float skph[SCH * 40];
    __shared__ float sposp[SCH * 32];
    __shared__ float swg[SCH];
    __shared__ float red[16][8];
    __shared__ float pref[8];

    unsigned e0 = 0;
    if (d == 0) e0 = *((volatile unsigned*)&g_epoch);

    for (int i = d; i < SCH * 40; i += 512) skph[i] = g_kph[(b * LL + l0) * 40 + i];
    sposp[d] = g_posph[l0 * 32 + d];

    // --- inline write gate: block-parallel exclusive jk-prefix at l0 ---
    {
        float acc8[8];
#pragma unroll
        for (int c = 0; c < 8; c++) acc8[c] = 0.f;
        for (int r = d; r < l0; r += 512) {
            const float4* p = (const float4*)(g_jk + (b * LL + r) * 8);
            float4 a0 = p[0], a1 = p[1];
            acc8[0] += a0.x; acc8[1] += a0.y; acc8[2] += a0.z; acc8[3] += a0.w;
            acc8[4] += a1.x; acc8[5] += a1.y; acc8[6] += a1.z; acc8[7] += a1.w;
        }
#pragma unroll
        for (int o = 16; o > 0; o >>= 1)
#pragma unroll
            for (int c = 0; c < 8; c++) acc8[c] += __shfl_xor_sync(0xffffffffu, acc8[c], o);
        if (lane == 0) {
#pragma unroll
            for (int c = 0; c < 8; c++) red[wrp][c] = acc8[c];
        }
        __syncthreads();
        if (d < 8) {
            float s = 0.f;
#pragma unroll
            for (int w = 0; w < 16; w++) s += red[w][d];
            pref[d] = s;
        }
        __syncthreads();
        if (d < 32) {
            float cr = (lane < 4) ? pref[2 * lane] : 0.f;
            float ci = (lane < 4) ? pref[2 * lane + 1] : 0.f;
            float rs = fminf(fmaxf(rscale[0], 1.f), 20.f);
            float th = fminf(fmaxf(rthr[0], 0.1f), 0.9f);
            float ss = sscale[0], sb = sbias[0];
            for (int l = 0; l < SCH; l++) {
                int lg = l0 + l;
                float mg = (lane < 4) ? sqrtf(cr * cr + ci * ci) : 0.f;
                mg += __shfl_xor_sync(0xffffffffu, mg, 1);
                mg += __shfl_xor_sync(0xffffffffu, mg, 2);
                if (lane == 0) {
                    float mag = mg * 0.25f;
                    float nres = mag * rsqrtf(fmaxf((float)lg, 1.f));
                    float sup = 0.5f * (1.f - tanhf(rs * (nres - th)));
                    float wg = 1.f / (1.f + expf(-(ss * (sup - 0.5f) + sb)));
                    swg[l] = wg;
                    g_wg[b * LL + lg] = wg;
                }
                if (lane < 4) {
                    cr += g_jk[(b * LL + lg) * 8 + 2 * lane];
                    ci += g_jk[(b * LL + lg) * 8 + 2 * lane + 1];
                }
            }
        }
    }
    __syncthreads();

    // --- chunk sums ---
    float ar[NCHAN], ai[NCHAN];
#pragma unroll
    for (int c = 0; c < NCHAN; c++) { ar[c] = 0.f; ai[c] = 0.f; }

    for (int l = 0; l < SCH; l++) {
        float v = g_V[(b * LL + l0 + l) * DD + d];
        float vg = v * swg[l];
        const float* kp = skph + l * 40;
        const float* pp = sposp + l * 32;
#pragma unroll
        for (int c = 0; c < 20; c++) {
            ar[c] += kp[2 * c] * vg;
            ai[c] += kp[2 * c + 1] * vg;
        }
#pragma unroll
        for (int p = 0; p < 16; p++) {
            ar[20 + p] += pp[2 * p] * v;
            ai[20 + p] += pp[2 * p + 1] * v;
        }
    }
#pragma unroll
    for (int c = 0; c < NCHAN; c++)
        g_S[((b * CCH + j) * NCHAN + c) * DD + d] = make_float2(ar[c], ai[c]);

    // --- grid barrier ---
    __threadfence();
    __syncthreads();
    if (d == 0) {
        unsigned a = atomicAdd(&g_count, 1);
        if (a == NBLK - 1) { g_count = 0; __threadfence(); atomicAdd(&g_epoch, 1); }
        else while (*((volatile unsigned*)&g_epoch) - e0 < 1u) {}
    }
    __syncthreads();

    // --- exclusive prefix over chunks (batched MLP-8) ---
    {
        int id = bx * 512 + d;
        if (id < BB * NCHAN * DD) {
            int d2 = id & (DD - 1);
            int c2 = (id >> 9) % NCHAN;
            int b2 = id / (NCHAN * DD);
            float2* base = g_S + (b2 * CCH * NCHAN + c2) * DD + d2;
            const int STRIDE = NCHAN * DD;
            float2 run = make_float2(0.f, 0.f);
#pragma unroll
            for (int g = 0; g < 8; g++) {
                float2 buf[8];
#pragma unroll
                for (int k = 0; k < 8; k++) buf[k] = base[(g * 8 + k) * STRIDE];
#pragma unroll
                for (int k = 0; k < 8; k++) {
                    float2 t = buf[k];
                    buf[k] = run;
                    run.x += t.x;
                    run.y += t.y;
                }
#pragma unroll
                for (int k = 0; k < 8; k++) base[(g * 8 + k) * STRIDE] = buf[k];
            }
        }
    }
}

// final scan + retrieval + inline gate + LayerNorm
__global__ __launch_bounds__(512) void final_kernel(const float* __restrict__ posw,
                                                    const float* __restrict__ lng,
                                                    const float* __restrict__ lnb,
                                                    const float* __restrict__ g2w,
                                                    const float* __restrict__ g2b)
{
    int j = blockIdx.x, b = blockIdx.y, d = threadIdx.x;
    int l0 = j * SCH;
    __shared__ float skph[SCH * 40];
    __shared__ float sqph[SCH * 40];
    __shared__ float sposp[SCH * 32];
    __shared__ float swg[SCH];
    __shared__ float sgate[SCH];
    __shared__ float sy[SCH][DD];

    for (int i = d; i < SCH * 40; i += 512) {
        skph[i] = g_kph[(b * LL + l0) * 40 + i];
        sqph[i] = g_qph[(b * LL + l0) * 40 + i];
    }
    sposp[d] = g_posph[l0 * 32 + d];
    if (d < SCH) swg[d] = g_wg[b * LL + l0 + d];

    // inline gate: warp w handles row (b*CCH + j)*16 + w
    {
        int w = d >> 5, ln = d & 31;
        int grow = (b * CCH + j) * SCH + w;
        float p = 0.f;
#pragma unroll
        for (int k = 0; k < 8; k++) {
            float v = g_hpre[grow * HG + ln + k * 32];
            float ge = 0.5f * v * (1.f + erff(v * 0.70710678118654752f));
            p += ge * g2w[ln + k * 32];
        }
#pragma unroll
        for (int o = 16; o > 0; o >>= 1) p += __shfl_xor_sync(0xffffffffu, p, o);
        if (ln == 0) sgate[w] = 1.f / (1.f + expf(-(p + g2b[0])));
    }
    __syncthreads();

    float spw = 1.f / (1.f + expf(-posw[0]));

    float ar[NCHAN], ai[NCHAN];
#pragma unroll
    for (int c = 0; c < NCHAN; c++) {
        float2 t = g_S[((b * CCH + j) * NCHAN + c) * DD + d];
        ar[c] = t.x;
        ai[c] = t.y;
    }

    for (int l = 0; l < SCH; l++) {
        int lg = l0 + l;
        float v = g_V[(b * LL + lg) * DD + d];
        float vg = v * swg[l];
        const float* kp = skph + l * 40;
        const float* qp = sqph + l * 40;
        const float* pp = sposp + l * 32;
        float r1 = 0.f, r2 = 0.f;
#pragma unroll
        for (int c = 0; c < 20; c++) {
            ar[c] += kp[2 * c] * vg;
            ai[c] += kp[2 * c + 1] * vg;
            r1 += ar[c] * qp[2 * c] + ai[c] * qp[2 * c + 1];
        }
#pragma unroll
        for (int p = 0; p < 16; p++) {
            ar[20 + p] += pp[2 * p] * v;
            ai[20 + p] += pp[2 * p + 1] * v;
            r2 += ar[20 + p] * pp[2 * p] + ai[20 + p] * pp[2 * p + 1];
        }
        float gl = sgate[l];
        sy[l][d] = (gl * r1 + (1.f - gl) * spw * r2) * rsqrtf(4.0f * (float)(lg + 1));
    }
    __syncthreads();

    // LayerNorm: one warp per row (16 warps, 16 rows)
    {
        int w = d >> 5, ln = d & 31;
        float vals[16];
        float s1 = 0.f, s2 = 0.f;
#pragma unroll
        for (int k = 0; k < 16; k++) {
            float t = sy[w][ln + k * 32];
            vals[k] = t;
            s1 += t;
            s2 += t * t;
        }
#pragma unroll
        for (int o = 16; o > 0; o >>= 1) {
            s1 += __shfl_xor_sync(0xffffffffu, s1, o);
            s2 += __shfl_xor_sync(0xffffffffu, s2, o);
        }
        float mu = s1 * (1.f / (float)DD);
        float var = s2 * (1.f / (float)DD) - mu * mu;
        float rstd = rsqrtf(var + 1e-5f);
        int base = (b * LL + l0 + w) * DD;
#pragma unroll
        for (int k = 0; k < 16; k++) {
            int d2 = ln + k * 32;
            float yn = (vals[k] - mu) * rstd * lng[d2] + lnb[d2];
            __nv_bfloat16 h = __float2bfloat16_rn(yn);
            g_ynh[base + d2] = h;
            g_ynl[base + d2] = __float2bfloat16_rn(yn - __bfloat162float(h));
        }
    }
}

// ===================== launch =====================
extern "C" void kernel_launch(void* const* d_in, const int* in_sizes, int n_in,
                              void* d_out, int out_size)
{
    const float* x      = (const float*)d_in[0];
    const float* keyp   = (const float*)d_in[1];
    const float* queryp = (const float*)d_in[2];
    const float* v_w    = (const float*)d_in[4];
    const float* v_b    = (const float*)d_in[5];
    const float* ln_g   = (const float*)d_in[6];
    const float* ln_b   = (const float*)d_in[7];
    const float* out_w  = (const float*)d_in[8];
    const float* out_b  = (const float*)d_in[9];
    const float* setw   = (const float*)d_in[10];
    const float* posf   = (const float*)d_in[11];
    const float* posw   = (const float*)d_in[12];
    const float* g1w    = (const float*)d_in[13];
    const float* g1b    = (const float*)d_in[14];
    const float* g2w    = (const float*)d_in[15];
    const float* g2b    = (const float*)d_in[16];
    const float* sscale = (const float*)d_in[19];
    const float* sbias  = (const float*)d_in[20];
    const float* rscale = (const float*)d_in[21];
    const float* rthr   = (const float*)d_in[22];
    float* out = (float*)d_out;

    cudaFuncSetAttribute(gemm_mma_kernel<false>,
                         cudaFuncAttributeMaxDynamicSharedMemorySize, GM_SMEM_BYTES);
    cudaFuncSetAttribute(gemm_mma_kernel<true>,
                         cudaFuncAttributeMaxDynamicSharedMemorySize, GM_SMEM_BYTES);

    float *pV, *pH;
    __nv_bfloat16 *pXh, *pXl, *pYh, *pYl, *pWvh, *pWvl, *pWoh, *pWol, *pWgh, *pWgl;
    cudaGetSymbolAddress((void**)&pV, g_V);
    cudaGetSymbolAddress((void**)&pH, g_hpre);
    cudaGetSymbolAddress((void**)&pXh, g_xh);
    cudaGetSymbolAddress((void**)&pXl, g_xl);
    cudaGetSymbolAddress((void**)&pYh, g_ynh);
    cudaGetSymbolAddress((void**)&pYl, g_ynl);
    cudaGetSymbolAddress((void**)&pWvh, g_wvh);
    cudaGetSymbolAddress((void**)&pWvl, g_wvl);
    cudaGetSymbolAddress((void**)&pWoh, g_woh);
    cudaGetSymbolAddress((void**)&pWol, g_wol);
    cudaGetSymbolAddress((void**)&pWgh, g_wgh);
    cudaGetSymbolAddress((void**)&pWgl, g_wgl);

    // fork s2 off the main (captured) stream
    cudaEventRecord(g_ss.evFork, 0);
    cudaStreamWaitEvent(g_ss.s2, g_ss.evFork, 0);

    // ---- s2: og converts (starts at t=0) ----
    convert_og_kernel<<<384, 256, 0, g_ss.s2>>>(out_w, g1w);

    // ---- s0: fused x/vw converts + phases ----
    convert_phase_kernel<<<1600, 256>>>(x, v_w, keyp, queryp, setw, posf);
    cudaEventRecord(g_ss.evConv, 0);
    cudaStreamWaitEvent(g_ss.s2, g_ss.evConv, 0);

    // ---- s0: V gemm ----
    gemm_mma_kernel<false><<<dim3(DD / 64, RR / 128), 256, GM_SMEM_BYTES>>>(
        pXh, pXl, pWvh, pWvl, v_b, nullptr, pV, DD);

    // ---- s2: H gemm ----
    gemm_mma_kernel<false><<<dim3(HG / 64, RR / 128), 256, GM_SMEM_BYTES, g_ss.s2>>>(
        pXh, pXl, pWgh, pWgl, g1b, nullptr, pH, HG);
    cudaEventRecord(g_ss.evH, g_ss.s2);

    // ---- s0: fused scan (chunk sums + wg + grid-bar + prefix) ----
    scan_kernel<<<NBLK, 512>>>(rscale, rthr, sscale, sbias);

    // ---- s0: final (needs gemm_H via evH) ----
    cudaStreamWaitEvent(0, g_ss.evH, 0);
    final_kernel<<<dim3(CCH, BB), 512>>>(posw, ln_g, ln_b, g2w, g2b);

    // ---- s0: output projection + residual ----
    gemm_mma_kernel<true><<<dim3(DD / 64, RR / 128), 256, GM_SMEM_BYTES>>>(
        pYh, pYl, pWoh, pWol, out_b, x, out, DD);
}

// round 15
// speedup vs baseline: 1.0003x; 1.0003x over previous
#include <cuda_runtime.h>
#include <cuda_bf16.h>
#include <math.h>
#include <stdint.h>

// Problem constants
#define BB 2
#define LL 1024
#define DD 512
#define RR (BB * LL)          // 2048 rows
#define TPJ 16                // total planes (NS*PP)
#define PDIM 16               // positional planes
#define NCHAN 36              // 16 bank + 4 cross + 16 positional
#define CCH 64                // chunks along L
#define SCH 16                // chunk size
#define HG 256                // g1 hidden

#define PI_F 3.14159265358979323846f

// ===================== base-ISA tensor helpers =====================
__device__ __forceinline__ uint32_t smem_u32(const void* p) {
    uint32_t a;
    asm("{ .reg .u64 t; cvta.to.shared.u64 t, %1; cvt.u32.u64 %0, t; }" : "=r"(a) : "l"(p));
    return a;
}
__device__ __forceinline__ void ldsm_x4(uint32_t* r, uint32_t addr) {
    asm volatile("ldmatrix.sync.aligned.m8n8.x4.shared.b16 {%0,%1,%2,%3}, [%4];"
                 : "=r"(r[0]), "=r"(r[1]), "=r"(r[2]), "=r"(r[3]) : "r"(addr));
}
__device__ __forceinline__ void mma16816(float* d, const uint32_t* a, const uint32_t* b) {
    asm volatile("mma.sync.aligned.m16n8k16.row.col.f32.bf16.bf16.f32 "
                 "{%0,%1,%2,%3}, {%4,%5,%6,%7}, {%8,%9}, {%0,%1,%2,%3};"
                 : "+f"(d[0]), "+f"(d[1]), "+f"(d[2]), "+f"(d[3])
                 : "r"(a[0]), "r"(a[1]), "r"(a[2]), "r"(a[3]), "r"(b[0]), "r"(b[1]));
}
#define CP_ASYNC16(sm, gp) \
    asm volatile("cp.async.cg.shared.global [%0], [%1], 16;" :: "r"(sm), "l"(gp))
#define CP_COMMIT() asm volatile("cp.async.commit_group;" ::: "memory")
#define CP_WAIT2() asm volatile("cp.async.wait_group 2;" ::: "memory")
#define CP_WAIT0() asm volatile("cp.async.wait_group 0;" ::: "memory")

// ===================== device scratch =====================
__device__ float2 g_S[BB * CCH * NCHAN * DD];
__device__ float  g_V[RR * DD];
__device__ float  g_hpre[RR * HG];
__device__ float  g_wg[RR];
__device__ float  g_kph[RR * 40];
__device__ float  g_qph[RR * 40];
__device__ float  g_jk[RR * 8];
__device__ float  g_posph[LL * 32];
__device__ __nv_bfloat16 g_xh[RR * DD], g_xl[RR * DD];
__device__ __nv_bfloat16 g_ynh[RR * DD], g_ynl[RR * DD];
__device__ __nv_bfloat16 g_wvh[DD * DD], g_wvl[DD * DD];
__device__ __nv_bfloat16 g_woh[DD * DD], g_wol[DD * DD];
__device__ __nv_bfloat16 g_wgh[HG * DD], g_wgl[HG * DD];

// ===================== side-stream infra (static init: pre-checkpoint) =====
__global__ void warm_kernel() {}
struct SideStreams {
    cudaStream_t s2;
    cudaEvent_t evFork, evConv, evH;
    SideStreams() {
        cudaStreamCreateWithFlags(&s2, cudaStreamNonBlocking);
        cudaEventCreateWithFlags(&evFork, cudaEventDisableTiming);
        cudaEventCreateWithFlags(&evConv, cudaEventDisableTiming);
        cudaEventCreateWithFlags(&evH, cudaEventDisableTiming);
        warm_kernel<<<1, 32, 0, s2>>>();
        cudaDeviceSynchronize();
    }
};
static SideStreams g_ss;

// ===================== weight transpose+split helper =====================
__device__ __forceinline__ void conv_w_tile(const float* W, __nv_bfloat16* Th,
                                            __nv_bfloat16* Tl, int N,
                                            int n0, int k0, int tid,
                                            float (*t)[33])
{
    int tx = tid & 31, ty = tid >> 5;   // 32 x 8
#pragma unroll
    for (int i = 0; i < 32; i += 8) t[ty + i][tx] = W[(k0 + ty + i) * N + n0 + tx];
    __syncthreads();
#pragma unroll
    for (int i = 0; i < 32; i += 8) {
        float v = t[tx][ty + i];
        __nv_bfloat16 h = __float2bfloat16_rn(v);
        Th[(n0 + ty + i) * DD + k0 + tx] = h;
        Tl[(n0 + ty + i) * DD + k0 + tx] = __float2bfloat16_rn(v - __bfloat162float(h));
    }
}

// ===================== fused: x split + v_w split + phases (one launch) ====
__global__ __launch_bounds__(256) void convert_phase_kernel(
    const float* __restrict__ x, const float* __restrict__ vw,
    const float* __restrict__ keyp, const float* __restrict__ queryp,
    const float* __restrict__ setw, const float* __restrict__ freqs)
{
    int bx = blockIdx.x, tid = threadIdx.x;
    if (bx < 1024) {
        int i = bx * 256 + tid;
        float4 v = ((const float4*)x)[i];
        float f[4] = {v.x, v.y, v.z, v.w};
        __nv_bfloat16 h[4], l[4];
#pragma unroll
        for (int k = 0; k < 4; k++) {
            h[k] = __float2bfloat16_rn(f[k]);
            l[k] = __float2bfloat16_rn(f[k] - __bfloat162float(h[k]));
        }
        ((__nv_bfloat162*)g_xh)[2 * i]     = __nv_bfloat162(h[0], h[1]);
        ((__nv_bfloat162*)g_xh)[2 * i + 1] = __nv_bfloat162(h[2], h[3]);
        ((__nv_bfloat162*)g_xl)[2 * i]     = __nv_bfloat162(l[0], l[1]);
        ((__nv_bfloat162*)g_xl)[2 * i + 1] = __nv_bfloat162(l[2], l[3]);
        return;
    }
    if (bx < 1280) {
        __shared__ float t[32][33];
        int rem = bx - 1024;
        conv_w_tile(vw, g_wvh, g_wvl, DD, (rem & 15) * 32, (rem >> 4) * 32, tid, t);
        return;
    }
    if (bx >= 1536) {
        int i = (bx - 1536) * 256 + tid;
        int l = i >> 4, p = i & 15;
        float a = ((float)l * freqs[p]) * (2.0f * PI_F);
        float s, c;
        sincosf(a, &s, &c);
        g_posph[l * 32 + 2 * p] = c;
        g_posph[l * 32 + 2 * p + 1] = s;
        return;
    }
    int row = (bx - 1280) * 8 + (tid >> 5);
    int lane = tid & 31;
    int t = lane & 15;
    const float* W = (lane < 16) ? keyp : queryp;
    const float* xr = x + row * DD;
    float acc = 0.f;
    for (int k = 0; k < DD; k++) acc += xr[k] * W[k * TPJ + t];
    float theta = tanhf(acc) * PI_F;

    float csum = theta;
    csum += __shfl_xor_sync(0xffffffffu, csum, 4);
    csum += __shfl_xor_sync(0xffffffffu, csum, 8);

    float w0 = setw[0], w1 = setw[1], w2 = setw[2], w3 = setw[3];
    float m = fmaxf(fmaxf(w0, w1), fmaxf(w2, w3));
    float e0 = expf(w0 - m), e1 = expf(w1 - m), e2 = expf(w2 - m), e3 = expf(w3 - m);
    float inv = 1.f / (e0 + e1 + e2 + e3);
    float wv[4] = {e0 * inv, e1 * inv, e2 * inv, e3 * inv};

    float s, c;
    sincosf(theta, &s, &c);
    if (lane < 16) {
        g_kph[row * 40 + 2 * t] = c;
        g_kph[row * 40 + 2 * t + 1] = s;
        if (t < 4) {
            float s2, c2;
            sincosf(csum, &s2, &c2);
            g_kph[row * 40 + 2 * (16 + t)] = c2;
            g_kph[row * 40 + 2 * (16 + t) + 1] = s2;
            g_jk[row * 8 + 2 * t] = c2;
            g_jk[row * 8 + 2 * t + 1] = s2;
        }
    } else {
        float wq = wv[t >> 2] * 0.2f;
        g_qph[row * 40 + 2 * t] = c * wq;
        g_qph[row * 40 + 2 * t + 1] = s * wq;
        if (t < 4) {
            float s2, c2;
            sincosf(csum, &s2, &c2);
            g_qph[row * 40 + 2 * (16 + t)] = c2 * 0.2f;
            g_qph[row * 40 + 2 * (16 + t) + 1] = s2 * 0.2f;
        }
    }
}

// convert out_w + g1_w (off critical path, s2)
__global__ __launch_bounds__(256) void convert_og_kernel(
    const float* __restrict__ ow, const float* __restrict__ g1w)
{
    __shared__ float t[32][33];
    int bx = blockIdx.x, tid = threadIdx.x;
    if (bx < 256) {
        conv_w_tile(ow, g_woh, g_wol, DD, (bx & 15) * 32, (bx >> 4) * 32, tid, t);
        return;
    }
    int rem = bx - 256;
    int n0 = (rem & 7) * 32, k0 = (rem >> 3) * 32;
    conv_w_tile(g1w, g_wgh, g_wgl, HG, n0, k0, tid, t);
}

// ===================== mma.sync GEMM (bf16 hi/lo split, 4-stage ring) ======
#define ST_EL 15360
#define NSTAGE 4
#define GM_SMEM_BYTES (NSTAGE * ST_EL * 2)

template <bool RESID>
__global__ void __launch_bounds__(256) gemm_mma_kernel(
    const __nv_bfloat16* __restrict__ Ah, const __nv_bfloat16* __restrict__ Al,
    const __nv_bfloat16* __restrict__ Bh, const __nv_bfloat16* __restrict__ Bl,
    const float* __restrict__ bias, const float* __restrict__ resid,
    float* __restrict__ C, int Ntot)
{
    extern __shared__ __nv_bfloat16 smem[];
    const int tid = threadIdx.x, lane = tid & 31, wid = tid >> 5;
    const int wm = (wid >> 1) * 32, wn = (wid & 1) * 32;
    const int bm = blockIdx.y * 128, bn = blockIdx.x * 64;
    const int K = 512;

    uint32_t sbase = smem_u32(smem);
    int arow = tid >> 2, aq = tid & 3;
    int brow = tid >> 2, bq = tid & 3;

    auto load_chunk = [&](int c, int s) {
        uint32_t st = sbase + s * ST_EL * 2;
        int k0 = c * 32;
#pragma unroll
        for (int i = 0; i < 2; i++) {
            int r = arow + i * 64;
            uint32_t so = st + (r * 40 + aq * 8) * 2;
            CP_ASYNC16(so, Ah + (bm + r) * K + k0 + aq * 8);
            CP_ASYNC16(so + 5120 * 2, Al + (bm + r) * K + k0 + aq * 8);
        }
        {
            uint32_t so = st + (10240 + brow * 40 + bq * 8) * 2;
            CP_ASYNC16(so, Bh + (bn + brow) * K + k0 + bq * 8);
            CP_ASYNC16(so + 2560 * 2, Bl + (bn + brow) * K + k0 + bq * 8);
        }
    };

    float acc[2][4][4];
#pragma unroll
    for (int mt = 0; mt < 2; mt++)
#pragma unroll
        for (int nt = 0; nt < 4; nt++)
#pragma unroll
            for (int e = 0; e < 4; e++) acc[mt][nt][e] = 0.f;

    // prologue: 3 chunks in flight
#pragma unroll
    for (int p = 0; p < 3; p++) { load_chunk(p, p); CP_COMMIT(); }

    int a_row = (lane & 7) + ((lane >> 3) & 1) * 8;
    int a_k16 = ((lane >> 4) & 1) * 16;
    int b_row = (lane & 7) + ((lane >> 4) & 1) * 8;
    int b_k16 = ((lane >> 3) & 1) * 16;

    for (int c = 0; c < 16; c++) {
        int s = c & (NSTAGE - 1);
        CP_WAIT2();               // oldest pending group (chunk c) complete
        __syncthreads();          // all threads past iter c-1 compute; safe to refill
        if (c + 3 < 16) { load_chunk(c + 3, (c + 3) & (NSTAGE - 1)); CP_COMMIT(); }

        uint32_t st = sbase + s * ST_EL * 2;
#pragma unroll
        for (int ks = 0; ks < 2; ks++) {
            uint32_t aH[8], aL[8], bH[8], bL[8];
#pragma unroll
            for (int mt = 0; mt < 2; mt++) {
                int row = wm + mt * 16 + a_row;
                uint32_t ad = st + (row * 40) * 2 + ks * 32 + a_k16;
                ldsm_x4(aH + mt * 4, ad);
                ldsm_x4(aL + mt * 4, ad + 5120 * 2);
            }
#pragma unroll
            for (int np = 0; np < 2; np++) {
                int row = wn + np * 16 + b_row;
                uint32_t bd = st + (10240 + row * 40) * 2 + ks * 32 + b_k16;
                ldsm_x4(bH + np * 4, bd);
                ldsm_x4(bL + np * 4, bd + 2560 * 2);
            }
#pragma unroll
            for (int mt = 0; mt < 2; mt++)
#pragma unroll
                for (int nt = 0; nt < 4; nt++) {
                    uint32_t* bh = bH + (nt >> 1) * 4 + (nt & 1) * 2;
                    uint32_t* bl = bL + (nt >> 1) * 4 + (nt & 1) * 2;
                    mma16816(acc[mt][nt], aH + mt * 4, bh);
                    mma16816(acc[mt][nt], aH + mt * 4, bl);
                    mma16816(acc[mt][nt], aL + mt * 4, bh);
                }
        }
    }

#pragma unroll
    for (int mt = 0; mt < 2; mt++)
#pragma unroll
        for (int nt = 0; nt < 4; nt++) {
            int col = bn + wn + nt * 8 + (lane & 3) * 2;
            float b0 = bias[col], b1 = bias[col + 1];
#pragma unroll
            for (int h = 0; h < 2; h++) {
                int row = bm + wm + mt * 16 + (lane >> 2) + h * 8;
                float2 o;
                o.x = acc[mt][nt][h * 2 + 0] + b0;
                o.y = acc[mt][nt][h * 2 + 1] + b1;
                if (RESID) {
                    float2 rr = *(const float2*)&resid[row * Ntot + col];
                    o.x += rr.x; o.y += rr.y;
                }
                *(float2*)&C[row * Ntot + col] = o;
            }
        }
}

// ===================== chunk sums + inline write gate =====================
__global__ __launch_bounds__(512) void chunk_sum_kernel(
    const float* __restrict__ rscale, const float* __restrict__ rthr,
    const float* __restrict__ sscale, const float* __restrict__ sbias)
{
    int j = blockIdx.x, b = blockIdx.y, d = threadIdx.x;
    int lane = d & 31, wrp = d >> 5;
    int l0 = j * SCH;
    __shared__ float skph[SCH * 40];
    __shared__ float sposp[SCH * 32];
    __shared__ float swg[SCH];
    __shared__ float red[16][8];
    __shared__ float pref[8];

    for (int i = d; i < SCH * 40; i += 512) skph[i] = g_kph[(b * LL + l0) * 40 + i];
    sposp[d] = g_posph[l0 * 32 + d];

    // inline write gate: block-parallel exclusive jk-prefix at l0
    {
        float acc8[8];
#pragma unroll
        for (int c = 0; c < 8; c++) acc8[c] = 0.f;
        for (int r = d; r < l0; r += 512) {
            const float4* p = (const float4*)(g_jk + (b * LL + r) * 8);
            float4 a0 = p[0], a1 = p[1];
            acc8[0] += a0.x; acc8[1] += a0.y; acc8[2] += a0.z; acc8[3] += a0.w;
            acc8[4] += a1.x; acc8[5] += a1.y; acc8[6] += a1.z; acc8[7] += a1.w;
        }
#pragma unroll
        for (int o = 16; o > 0; o >>= 1)
#pragma unroll
            for (int c = 0; c < 8; c++) acc8[c] += __shfl_xor_sync(0xffffffffu, acc8[c], o);
        if (lane == 0) {
#pragma unroll
            for (int c = 0; c < 8; c++) red[wrp][c] = acc8[c];
        }
        __syncthreads();
        if (d < 8) {
            float s = 0.f;
#pragma unroll
            for (int w = 0; w < 16; w++) s += red[w][d];
            pref[d] = s;
        }
        __syncthreads();
        if (d < 32) {
            float cr = (lane < 4) ? pref[2 * lane] : 0.f;
            float ci = (lane < 4) ? pref[2 * lane + 1] : 0.f;
            float rs = fminf(fmaxf(rscale[0], 1.f), 20.f);
            float th = fminf(fmaxf(rthr[0], 0.1f), 0.9f);
            float ss = sscale[0], sb = sbias[0];
            for (int l = 0; l < SCH; l++) {
                int lg = l0 + l;
                float mg = (lane < 4) ? sqrtf(cr * cr + ci * ci) : 0.f;
                mg += __shfl_xor_sync(0xffffffffu, mg, 1);
                mg += __shfl_xor_sync(0xffffffffu, mg, 2);
                if (lane == 0) {
                    float mag = mg * 0.25f;
                    float nres = mag * rsqrtf(fmaxf((float)lg, 1.f));
                    float sup = 0.5f * (1.f - tanhf(rs * (nres - th)));
                    float wg = 1.f / (1.f + expf(-(ss * (sup - 0.5f) + sb)));
                    swg[l] = wg;
                    g_wg[b * LL + lg] = wg;
                }
                if (lane < 4) {
                    cr += g_jk[(b * LL + lg) * 8 + 2 * lane];
                    ci += g_jk[(b * LL + lg) * 8 + 2 * lane + 1];
                }
            }
        }
    }
    __syncthreads();

    float ar[NCHAN], ai[NCHAN];
#pragma unroll
    for (int c = 0; c < NCHAN; c++) { ar[c] = 0.f; ai[c] = 0.f; }

    for (int l = 0; l < SCH; l++) {
        float v = g_V[(b * LL + l0 + l) * DD + d];
        float vg = v * swg[l];
        const float* kp = skph + l * 40;
        const float* pp = sposp + l * 32;
#pragma unroll
        for (int c = 0; c < 20; c++) {
            ar[c] += kp[2 * c] * vg;
            ai[c] += kp[2 * c + 1] * vg;
        }
#pragma unroll
        for (int p = 0; p < 16; p++) {
            ar[20 + p] += pp[2 * p] * v;
            ai[20 + p] += pp[2 * p + 1] * v;
        }
    }
#pragma unroll
    for (int c = 0; c < NCHAN; c++)
        g_S[((b * CCH + j) * NCHAN + c) * DD + d] = make_float2(ar[c], ai[c]);
}

// exclusive prefix over chunks — batched loads/stores for MLP=8
__global__ void prefix_kernel()
{
    int id = blockIdx.x * blockDim.x + threadIdx.x;
    if (id >= BB * NCHAN * DD) return;
    int d = id & (DD - 1);
    int c = (id >> 9) % NCHAN;
    int b = id / (NCHAN * DD);
    float2* base = g_S + (b * CCH * NCHAN + c) * DD + d;
    const int STRIDE = NCHAN * DD;
    float2 run = make_float2(0.f, 0.f);
#pragma unroll
    for (int g = 0; g < 8; g++) {
        float2 buf[8];
#pragma unroll
        for (int k = 0; k < 8; k++) buf[k] = base[(g * 8 + k) * STRIDE];
#pragma unroll
        for (int k = 0; k < 8; k++) {
            float2 t = buf[k];
            buf[k] = run;
            run.x += t.x;
            run.y += t.y;
        }
#pragma unroll
        for (int k = 0; k < 8; k++) base[(g * 8 + k) * STRIDE] = buf[k];
    }
}

// final scan + retrieval + inline gate + LayerNorm
__global__ __launch_bounds__(512) void final_kernel(const float* __restrict__ posw,
                                                    const float* __restrict__ lng,
                                                    const float* __restrict__ lnb,
                                                    const float* __restrict__ g2w,
                                                    const float* __restrict__ g2b)
{
    int j = blockIdx.x, b = blockIdx.y, d = threadIdx.x;
    int l0 = j * SCH;
    __shared__ float skph[SCH * 40];
    __shared__ float sqph[SCH * 40];
    __shared__ float sposp[SCH * 32];
    __shared__ float swg[SCH];
    __shared__ float sgate[SCH];
    __shared__ float sy[SCH][DD];

    for (int i = d; i < SCH * 40; i += 512) {
        skph[i] = g_kph[(b * LL + l0) * 40 + i];
        sqph[i] = g_qph[(b * LL + l0) * 40 + i];
    }
    sposp[d] = g_posph[l0 * 32 + d];
    if (d < SCH) swg[d] = g_wg[b * LL + l0 + d];

    {
        int w = d >> 5, ln = d & 31;
        int grow = (b * CCH + j) * SCH + w;
        float p = 0.f;
#pragma unroll
        for (int k = 0; k < 8; k++) {
            float v = g_hpre[grow * HG + ln + k * 32];
            float ge = 0.5f * v * (1.f + erff(v * 0.70710678118654752f));
            p += ge * g2w[ln + k * 32];
        }
#pragma unroll
        for (int o = 16; o > 0; o >>= 1) p += __shfl_xor_sync(0xffffffffu, p, o);
        if (ln == 0) sgate[w] = 1.f / (1.f + expf(-(p + g2b[0])));
    }
    __syncthreads();

    float spw = 1.f / (1.f + expf(-posw[0]));

    float ar[NCHAN], ai[NCHAN];
#pragma unroll
    for (int c = 0; c < NCHAN; c++) {
        float2 t = g_S[((b * CCH + j) * NCHAN + c) * DD + d];
        ar[c] = t.x;
        ai[c] = t.y;
    }

    for (int l = 0; l < SCH; l++) {
        int lg = l0 + l;
        float v = g_V[(b * LL + lg) * DD + d];
        float vg = v * swg[l];
        const float* kp = skph + l * 40;
        const float* qp = sqph + l * 40;
        const float* pp = sposp + l * 32;
        float r1 = 0.f, r2 = 0.f;
#pragma unroll
        for (int c = 0; c < 20; c++) {
            ar[c] += kp[2 * c] * vg;
            ai[c] += kp[2 * c + 1] * vg;
            r1 += ar[c] * qp[2 * c] + ai[c] * qp[2 * c + 1];
        }
#pragma unroll
        for (int p = 0; p < 16; p++) {
            ar[20 + p] += pp[2 * p] * v;
            ai[20 + p] += pp[2 * p + 1] * v;
            r2 += ar[20 + p] * pp[2 * p] + ai[20 + p] * pp[2 * p + 1];
        }
        float gl = sgate[l];
        sy[l][d] = (gl * r1 + (1.f - gl) * spw * r2) * rsqrtf(4.0f * (float)(lg + 1));
    }
    __syncthreads();

    {
        int w = d >> 5, ln = d & 31;
        float vals[16];
        float s1 = 0.f, s2 = 0.f;
#pragma unroll
        for (int k = 0; k < 16; k++) {
            float t = sy[w][ln + k * 32];
            vals[k] = t;
            s1 += t;
            s2 += t * t;
        }
#pragma unroll
        for (int o = 16; o > 0; o >>= 1) {
            s1 += __shfl_xor_sync(0xffffffffu, s1, o);
            s2 += __shfl_xor_sync(0xffffffffu, s2, o);
        }
        float mu = s1 * (1.f / (float)DD);
        float var = s2 * (1.f / (float)DD) - mu * mu;
        float rstd = rsqrtf(var + 1e-5f);
        int base = (b * LL + l0 + w) * DD;
#pragma unroll
        for (int k = 0; k < 16; k++) {
            int d2 = ln + k * 32;
            float yn = (vals[k] - mu) * rstd * lng[d2] + lnb[d2];
            __nv_bfloat16 h = __float2bfloat16_rn(yn);
            g_ynh[base + d2] = h;
            g_ynl[base + d2] = __float2bfloat16_rn(yn - __bfloat162float(h));
        }
    }
}

// ===================== launch =====================
extern "C" void kernel_launch(void* const* d_in, const int* in_sizes, int n_in,
                              void* d_out, int out_size)
{
    const float* x      = (const float*)d_in[0];
    const float* keyp   = (const float*)d_in[1];
    const float* queryp = (const float*)d_in[2];
    const float* v_w    = (const float*)d_in[4];
    const float* v_b    = (const float*)d_in[5];
    const float* ln_g   = (const float*)d_in[6];
    const float* ln_b   = (const float*)d_in[7];
    const float* out_w  = (const float*)d_in[8];
    const float* out_b  = (const float*)d_in[9];
    const float* setw   = (const float*)d_in[10];
    const float* posf   = (const float*)d_in[11];
    const float* posw   = (const float*)d_in[12];
    const float* g1w    = (const float*)d_in[13];
    const float* g1b    = (const float*)d_in[14];
    const float* g2w    = (const float*)d_in[15];
    const float* g2b    = (const float*)d_in[16];
    const float* sscale = (const float*)d_in[19];
    const float* sbias  = (const float*)d_in[20];
    const float* rscale = (const float*)d_in[21];
    const float* rthr   = (const float*)d_in[22];
    float* out = (float*)d_out;

    cudaFuncSetAttribute(gemm_mma_kernel<false>,
                         cudaFuncAttributeMaxDynamicSharedMemorySize, GM_SMEM_BYTES);
    cudaFuncSetAttribute(gemm_mma_kernel<true>,
                         cudaFuncAttributeMaxDynamicSharedMemorySize, GM_SMEM_BYTES);

    float *pV, *pH;
    __nv_bfloat16 *pXh, *pXl, *pYh, *pYl, *pWvh, *pWvl, *pWoh, *pWol, *pWgh, *pWgl;
    cudaGetSymbolAddress((void**)&pV, g_V);
    cudaGetSymbolAddress((void**)&pH, g_hpre);
    cudaGetSymbolAddress((void**)&pXh, g_xh);
    cudaGetSymbolAddress((void**)&pXl, g_xl);
    cudaGetSymbolAddress((void**)&pYh, g_ynh);
    cudaGetSymbolAddress((void**)&pYl, g_ynl);
    cudaGetSymbolAddress((void**)&pWvh, g_wvh);
    cudaGetSymbolAddress((void**)&pWvl, g_wvl);
    cudaGetSymbolAddress((void**)&pWoh, g_woh);
    cudaGetSymbolAddress((void**)&pWol, g_wol);
    cudaGetSymbolAddress((void**)&pWgh, g_wgh);
    cudaGetSymbolAddress((void**)&pWgl, g_wgl);

    // fork s2 off the main (captured) stream
    cudaEventRecord(g_ss.evFork, 0);
    cudaStreamWaitEvent(g_ss.s2, g_ss.evFork, 0);

    // ---- s2: og converts (starts at t=0) ----
    convert_og_kernel<<<384, 256, 0, g_ss.s2>>>(out_w, g1w);

    // ---- s0: fused x/vw converts + phases ----
    convert_phase_kernel<<<1600, 256>>>(x, v_w, keyp, queryp, setw, posf);
    cudaEventRecord(g_ss.evConv, 0);
    cudaStreamWaitEvent(g_ss.s2, g_ss.evConv, 0);

    // ---- s0: V gemm ----
    gemm_mma_kernel<false><<<dim3(DD / 64, RR / 128), 256, GM_SMEM_BYTES>>>(
        pXh, pXl, pWvh, pWvl, v_b, nullptr, pV, DD);

    // ---- s2: H gemm ----
    gemm_mma_kernel<false><<<dim3(HG / 64, RR / 128), 256, GM_SMEM_BYTES, g_ss.s2>>>(
        pXh, pXl, pWgh, pWgl, g1b, nullptr, pH, HG);
    cudaEventRecord(g_ss.evH, g_ss.s2);

    // ---- s0: scan chain ----
    chunk_sum_kernel<<<dim3(CCH, BB), 512>>>(rscale, rthr, sscale, sbias);
    prefix_kernel<<<(BB * NCHAN * DD + 255) / 256, 256>>>();

    // ---- s0: final (needs gemm_H via evH) ----
    cudaStreamWaitEvent(0, g_ss.evH, 0);
    final_kernel<<<dim3(CCH, BB), 512>>>(posw, ln_g, ln_b, g2w, g2b);

    // ---- s0: output projection + residual ----
    gemm_mma_kernel<true><<<dim3(DD / 64, RR / 128), 256, GM_SMEM_BYTES>>>(
        pYh, pYl, pWoh, pWol, out_b, x, out, DD);
}

// round 16
// speedup vs baseline: 1.0025x; 1.0022x over previous
#include <cuda_runtime.h>
#include <cuda_bf16.h>
#include <math.h>
#include <stdint.h>

// Problem constants
#define BB 2
#define LL 1024
#define DD 512
#define RR (BB * LL)          // 2048 rows
#define TPJ 16                // total planes (NS*PP)
#define PDIM 16               // positional planes
#define NCHAN 36              // 16 bank + 4 cross + 16 positional
#define CCH 64                // chunks along L
#define SCH 16                // chunk size
#define HG 256                // g1 hidden

#define PI_F 3.14159265358979323846f

// ===================== base-ISA tensor helpers =====================
__device__ __forceinline__ uint32_t smem_u32(const void* p) {
    uint32_t a;
    asm("{ .reg .u64 t; cvta.to.shared.u64 t, %1; cvt.u32.u64 %0, t; }" : "=r"(a) : "l"(p));
    return a;
}
__device__ __forceinline__ void ldsm_x4(uint32_t* r, uint32_t addr) {
    asm volatile("ldmatrix.sync.aligned.m8n8.x4.shared.b16 {%0,%1,%2,%3}, [%4];"
                 : "=r"(r[0]), "=r"(r[1]), "=r"(r[2]), "=r"(r[3]) : "r"(addr));
}
__device__ __forceinline__ void mma16816(float* d, const uint32_t* a, const uint32_t* b) {
    asm volatile("mma.sync.aligned.m16n8k16.row.col.f32.bf16.bf16.f32 "
                 "{%0,%1,%2,%3}, {%4,%5,%6,%7}, {%8,%9}, {%0,%1,%2,%3};"
                 : "+f"(d[0]), "+f"(d[1]), "+f"(d[2]), "+f"(d[3])
                 : "r"(a[0]), "r"(a[1]), "r"(a[2]), "r"(a[3]), "r"(b[0]), "r"(b[1]));
}
#define CP_ASYNC16(sm, gp) \
    asm volatile("cp.async.cg.shared.global [%0], [%1], 16;" :: "r"(sm), "l"(gp))
#define CP_COMMIT() asm volatile("cp.async.commit_group;" ::: "memory")
#define CP_WAIT1() asm volatile("cp.async.wait_group 1;" ::: "memory")
#define CP_WAIT0() asm volatile("cp.async.wait_group 0;" ::: "memory")

// ===================== device scratch =====================
__device__ float2 g_S[BB * CCH * NCHAN * DD];
__device__ float  g_V[RR * DD];
__device__ float  g_hpre[RR * HG];
__device__ float  g_wg[RR];
__device__ float  g_kph[RR * 40];
__device__ float  g_qph[RR * 40];
__device__ float  g_jk[RR * 8];
__device__ float  g_posph[LL * 32];
__device__ __nv_bfloat16 g_xh[RR * DD], g_xl[RR * DD];
__device__ __nv_bfloat16 g_ynh[RR * DD], g_ynl[RR * DD];
__device__ __nv_bfloat16 g_wvh[DD * DD], g_wvl[DD * DD];
__device__ __nv_bfloat16 g_woh[DD * DD], g_wol[DD * DD];
__device__ __nv_bfloat16 g_wgh[HG * DD], g_wgl[HG * DD];

// ===================== side-stream infra (static init: pre-checkpoint) =====
__global__ void warm_kernel() {}
struct SideStreams {
    cudaStream_t s2;
    cudaEvent_t evFork, evOG;
    SideStreams() {
        cudaStreamCreateWithFlags(&s2, cudaStreamNonBlocking);
        cudaEventCreateWithFlags(&evFork, cudaEventDisableTiming);
        cudaEventCreateWithFlags(&evOG, cudaEventDisableTiming);
        warm_kernel<<<1, 32, 0, s2>>>();
        cudaDeviceSynchronize();
    }
};
static SideStreams g_ss;

// ===================== weight transpose+split helper =====================
__device__ __forceinline__ void conv_w_tile(const float* W, __nv_bfloat16* Th,
                                            __nv_bfloat16* Tl, int N,
                                            int n0, int k0, int tid,
                                            float (*t)[33])
{
    int tx = tid & 31, ty = tid >> 5;   // 32 x 8
#pragma unroll
    for (int i = 0; i < 32; i += 8) t[ty + i][tx] = W[(k0 + ty + i) * N + n0 + tx];
    __syncthreads();
#pragma unroll
    for (int i = 0; i < 32; i += 8) {
        float v = t[tx][ty + i];
        __nv_bfloat16 h = __float2bfloat16_rn(v);
        Th[(n0 + ty + i) * DD + k0 + tx] = h;
        Tl[(n0 + ty + i) * DD + k0 + tx] = __float2bfloat16_rn(v - __bfloat162float(h));
    }
}

// ===================== fused: x split + v_w/g1_w split + phases ===========
// grid 1728: [0,1024) x-split, [1024,1280) v_w, [1280,1408) g1_w,
// [1408,1664) proj phases, [1664,1728) positional phases
__global__ __launch_bounds__(256) void convert_phase_kernel(
    const float* __restrict__ x, const float* __restrict__ vw,
    const float* __restrict__ g1w,
    const float* __restrict__ keyp, const float* __restrict__ queryp,
    const float* __restrict__ setw, const float* __restrict__ freqs)
{
    int bx = blockIdx.x, tid = threadIdx.x;
    if (bx < 1024) {
        int i = bx * 256 + tid;
        float4 v = ((const float4*)x)[i];
        float f[4] = {v.x, v.y, v.z, v.w};
        __nv_bfloat16 h[4], l[4];
#pragma unroll
        for (int k = 0; k < 4; k++) {
            h[k] = __float2bfloat16_rn(f[k]);
            l[k] = __float2bfloat16_rn(f[k] - __bfloat162float(h[k]));
        }
        ((__nv_bfloat162*)g_xh)[2 * i]     = __nv_bfloat162(h[0], h[1]);
        ((__nv_bfloat162*)g_xh)[2 * i + 1] = __nv_bfloat162(h[2], h[3]);
        ((__nv_bfloat162*)g_xl)[2 * i]     = __nv_bfloat162(l[0], l[1]);
        ((__nv_bfloat162*)g_xl)[2 * i + 1] = __nv_bfloat162(l[2], l[3]);
        return;
    }
    if (bx < 1280) {
        __shared__ float t[32][33];
        int rem = bx - 1024;
        conv_w_tile(vw, g_wvh, g_wvl, DD, (rem & 15) * 32, (rem >> 4) * 32, tid, t);
        return;
    }
    if (bx < 1408) {
        __shared__ float t[32][33];
        int rem = bx - 1280;
        conv_w_tile(g1w, g_wgh, g_wgl, HG, (rem & 7) * 32, (rem >> 3) * 32, tid, t);
        return;
    }
    if (bx >= 1664) {
        int i = (bx - 1664) * 256 + tid;
        int l = i >> 4, p = i & 15;
        float a = ((float)l * freqs[p]) * (2.0f * PI_F);
        float s, c;
        sincosf(a, &s, &c);
        g_posph[l * 32 + 2 * p] = c;
        g_posph[l * 32 + 2 * p + 1] = s;
        return;
    }
    int row = (bx - 1408) * 8 + (tid >> 5);
    int lane = tid & 31;
    int t = lane & 15;
    const float* W = (lane < 16) ? keyp : queryp;
    const float* xr = x + row * DD;
    float acc = 0.f;
    for (int k = 0; k < DD; k++) acc += xr[k] * W[k * TPJ + t];
    float theta = tanhf(acc) * PI_F;

    float csum = theta;
    csum += __shfl_xor_sync(0xffffffffu, csum, 4);
    csum += __shfl_xor_sync(0xffffffffu, csum, 8);

    float w0 = setw[0], w1 = setw[1], w2 = setw[2], w3 = setw[3];
    float m = fmaxf(fmaxf(w0, w1), fmaxf(w2, w3));
    float e0 = expf(w0 - m), e1 = expf(w1 - m), e2 = expf(w2 - m), e3 = expf(w3 - m);
    float inv = 1.f / (e0 + e1 + e2 + e3);
    float wv[4] = {e0 * inv, e1 * inv, e2 * inv, e3 * inv};

    float s, c;
    sincosf(theta, &s, &c);
    if (lane < 16) {
        g_kph[row * 40 + 2 * t] = c;
        g_kph[row * 40 + 2 * t + 1] = s;
        if (t < 4) {
            float s2, c2;
            sincosf(csum, &s2, &c2);
            g_kph[row * 40 + 2 * (16 + t)] = c2;
            g_kph[row * 40 + 2 * (16 + t) + 1] = s2;
            g_jk[row * 8 + 2 * t] = c2;
            g_jk[row * 8 + 2 * t + 1] = s2;
        }
    } else {
        float wq = wv[t >> 2] * 0.2f;
        g_qph[row * 40 + 2 * t] = c * wq;
        g_qph[row * 40 + 2 * t + 1] = s * wq;
        if (t < 4) {
            float s2, c2;
            sincosf(csum, &s2, &c2);
            g_qph[row * 40 + 2 * (16 + t)] = c2 * 0.2f;
            g_qph[row * 40 + 2 * (16 + t) + 1] = s2 * 0.2f;
        }
    }
}

// convert out_w (off critical path, s2)
__global__ __launch_bounds__(256) void convert_og_kernel(const float* __restrict__ ow)
{
    __shared__ float t[32][33];
    int bx = blockIdx.x, tid = threadIdx.x;
    conv_w_tile(ow, g_woh, g_wol, DD, (bx & 15) * 32, (bx >> 4) * 32, tid, t);
}

// ===================== mma.sync GEMM core (3-stage ring) ====================
#define ST_EL 15360
#define NSTAGE 3
#define GM_SMEM_BYTES (NSTAGE * ST_EL * 2)

// shared GEMM body: computes 128x64 tile of A(2048x512) @ B(64 rows of 512)^T
template <bool RESID>
__device__ __forceinline__ void gemm_body(
    __nv_bfloat16* smem,
    const __nv_bfloat16* __restrict__ Ah, const __nv_bfloat16* __restrict__ Al,
    const __nv_bfloat16* __restrict__ Bh, const __nv_bfloat16* __restrict__ Bl,
    const float* __restrict__ bias, const float* __restrict__ resid,
    float* __restrict__ C, int Ntot, int bm, int bn, int cb)
{
    const int tid = threadIdx.x, lane = tid & 31, wid = tid >> 5;
    const int wm = (wid >> 1) * 32, wn = (wid & 1) * 32;
    const int K = 512;

    uint32_t sbase = smem_u32(smem);
    int arow = tid >> 2, aq = tid & 3;
    int brow = tid >> 2, bq = tid & 3;

    auto load_chunk = [&](int c, int s) {
        uint32_t st = sbase + s * ST_EL * 2;
        int k0 = c * 32;
#pragma unroll
        for (int i = 0; i < 2; i++) {
            int r = arow + i * 64;
            uint32_t so = st + (r * 40 + aq * 8) * 2;
            CP_ASYNC16(so, Ah + (bm + r) * K + k0 + aq * 8);
            CP_ASYNC16(so + 5120 * 2, Al + (bm + r) * K + k0 + aq * 8);
        }
        {
            uint32_t so = st + (10240 + brow * 40 + bq * 8) * 2;
            CP_ASYNC16(so, Bh + (bn + brow) * K + k0 + bq * 8);
            CP_ASYNC16(so + 2560 * 2, Bl + (bn + brow) * K + k0 + bq * 8);
        }
    };

    float acc[2][4][4];
#pragma unroll
    for (int mt = 0; mt < 2; mt++)
#pragma unroll
        for (int nt = 0; nt < 4; nt++)
#pragma unroll
            for (int e = 0; e < 4; e++) acc[mt][nt][e] = 0.f;

    load_chunk(0, 0); CP_COMMIT();
    load_chunk(1, 1); CP_COMMIT();

    int a_row = (lane & 7) + ((lane >> 3) & 1) * 8;
    int a_k16 = ((lane >> 4) & 1) * 16;
    int b_row = (lane & 7) + ((lane >> 4) & 1) * 8;
    int b_k16 = ((lane >> 3) & 1) * 16;

    for (int c = 0; c < 16; c++) {
        int s = c % NSTAGE;
        if (c + 1 < 16) CP_WAIT1(); else CP_WAIT0();
        __syncthreads();
        if (c + 2 < 16) { load_chunk(c + 2, (c + 2) % NSTAGE); CP_COMMIT(); }

        uint32_t st = sbase + s * ST_EL * 2;
#pragma unroll
        for (int ks = 0; ks < 2; ks++) {
            uint32_t aH[8], aL[8], bH[8], bL[8];
#pragma unroll
            for (int mt = 0; mt < 2; mt++) {
                int row = wm + mt * 16 + a_row;
                uint32_t ad = st + (row * 40) * 2 + ks * 32 + a_k16;
                ldsm_x4(aH + mt * 4, ad);
                ldsm_x4(aL + mt * 4, ad + 5120 * 2);
            }
#pragma unroll
            for (int np = 0; np < 2; np++) {
                int row = wn + np * 16 + b_row;
                uint32_t bd = st + (10240 + row * 40) * 2 + ks * 32 + b_k16;
                ldsm_x4(bH + np * 4, bd);
                ldsm_x4(bL + np * 4, bd + 2560 * 2);
            }
#pragma unroll
            for (int mt = 0; mt < 2; mt++)
#pragma unroll
                for (int nt = 0; nt < 4; nt++) {
                    uint32_t* bh = bH + (nt >> 1) * 4 + (nt & 1) * 2;
                    uint32_t* bl = bL + (nt >> 1) * 4 + (nt & 1) * 2;
                    mma16816(acc[mt][nt], aH + mt * 4, bh);
                    mma16816(acc[mt][nt], aH + mt * 4, bl);
                    mma16816(acc[mt][nt], aL + mt * 4, bh);
                }
        }
    }

#pragma unroll
    for (int mt = 0; mt < 2; mt++)
#pragma unroll
        for (int nt = 0; nt < 4; nt++) {
            int col = cb + wn + nt * 8 + (lane & 3) * 2;
            float b0 = bias[col], b1 = bias[col + 1];
#pragma unroll
            for (int h = 0; h < 2; h++) {
                int row = bm + wm + mt * 16 + (lane >> 2) + h * 8;
                float2 o;
                o.x = acc[mt][nt][h * 2 + 0] + b0;
                o.y = acc[mt][nt][h * 2 + 1] + b1;
                if (RESID) {
                    float2 rr = *(const float2*)&resid[row * Ntot + col];
                    o.x += rr.x; o.y += rr.y;
                }
                *(float2*)&C[row * Ntot + col] = o;
            }
        }
}

// merged V + H gemm: blockIdx.x 0..7 -> V (N=512), 8..11 -> H (N=256)
__global__ void __launch_bounds__(256) gemm_vh_kernel(
    const float* __restrict__ v_b, const float* __restrict__ g1b)
{
    extern __shared__ __nv_bfloat16 smem[];
    int bxx = blockIdx.x;
    int bm = blockIdx.y * 128;
    if (bxx < 8) {
        gemm_body<false>(smem, g_xh, g_xl, g_wvh, g_wvl, v_b, nullptr,
                         g_V, DD, bm, bxx * 64, bxx * 64);
    } else {
        int bn = (bxx - 8) * 64;
        gemm_body<false>(smem, g_xh, g_xl, g_wgh, g_wgl, g1b, nullptr,
                         g_hpre, HG, bm, bn, bn);
    }
}

// output gemm with residual
__global__ void __launch_bounds__(256) gemm_out_kernel(
    const float* __restrict__ out_b, const float* __restrict__ x,
    float* __restrict__ out)
{
    extern __shared__ __nv_bfloat16 smem[];
    int bn = blockIdx.x * 64, bm = blockIdx.y * 128;
    gemm_body<true>(smem, g_ynh, g_ynl, g_woh, g_wol, out_b, x, out, DD, bm, bn, bn);
}

// ===================== chunk sums + inline write gate =====================
__global__ __launch_bounds__(512) void chunk_sum_kernel(
    const float* __restrict__ rscale, const float* __restrict__ rthr,
    const float* __restrict__ sscale, const float* __restrict__ sbias)
{
    int j = blockIdx.x, b = blockIdx.y, d = threadIdx.x;
    int lane = d & 31, wrp = d >> 5;
    int l0 = j * SCH;
    __shared__ float skph[SCH * 40];
    __shared__ float sposp[SCH * 32];
    __shared__ float swg[SCH];
    __shared__ float red[16][8];
    __shared__ float pref[8];

    for (int i = d; i < SCH * 40; i += 512) skph[i] = g_kph[(b * LL + l0) * 40 + i];
    sposp[d] = g_posph[l0 * 32 + d];

    {
        float acc8[8];
#pragma unroll
        for (int c = 0; c < 8; c++) acc8[c] = 0.f;
        for (int r = d; r < l0; r += 512) {
            const float4* p = (const float4*)(g_jk + (b * LL + r) * 8);
            float4 a0 = p[0], a1 = p[1];
            acc8[0] += a0.x; acc8[1] += a0.y; acc8[2] += a0.z; acc8[3] += a0.w;
            acc8[4] += a1.x; acc8[5] += a1.y; acc8[6] += a1.z; acc8[7] += a1.w;
        }
#pragma unroll
        for (int o = 16; o > 0; o >>= 1)
#pragma unroll
            for (int c = 0; c < 8; c++) acc8[c] += __shfl_xor_sync(0xffffffffu, acc8[c], o);
        if (lane == 0) {
#pragma unroll
            for (int c = 0; c < 8; c++) red[wrp][c] = acc8[c];
        }
        __syncthreads();
        if (d < 8) {
            float s = 0.f;
#pragma unroll
            for (int w = 0; w < 16; w++) s += red[w][d];
            pref[d] = s;
        }
        __syncthreads();
        if (d < 32) {
            float cr = (lane < 4) ? pref[2 * lane] : 0.f;
            float ci = (lane < 4) ? pref[2 * lane + 1] : 0.f;
            float rs = fminf(fmaxf(rscale[0], 1.f), 20.f);
            float th = fminf(fmaxf(rthr[0], 0.1f), 0.9f);
            float ss = sscale[0], sb = sbias[0];
            for (int l = 0; l < SCH; l++) {
                int lg = l0 + l;
                float mg = (lane < 4) ? sqrtf(cr * cr + ci * ci) : 0.f;
                mg += __shfl_xor_sync(0xffffffffu, mg, 1);
                mg += __shfl_xor_sync(0xffffffffu, mg, 2);
                if (lane == 0) {
                    float mag = mg * 0.25f;
                    float nres = mag * rsqrtf(fmaxf((float)lg, 1.f));
                    float sup = 0.5f * (1.f - tanhf(rs * (nres - th)));
                    float wg = 1.f / (1.f + expf(-(ss * (sup - 0.5f) + sb)));
                    swg[l] = wg;
                    g_wg[b * LL + lg] = wg;
                }
                if (lane < 4) {
                    cr += g_jk[(b * LL + lg) * 8 + 2 * lane];
                    ci += g_jk[(b * LL + lg) * 8 + 2 * lane + 1];
                }
            }
        }
    }
    __syncthreads();

    float ar[NCHAN], ai[NCHAN];
#pragma unroll
    for (int c = 0; c < NCHAN; c++) { ar[c] = 0.f; ai[c] = 0.f; }

    for (int l = 0; l < SCH; l++) {
        float v = g_V[(b * LL + l0 + l) * DD + d];
        float vg = v * swg[l];
        const float* kp = skph + l * 40;
        const float* pp = sposp + l * 32;
#pragma unroll
        for (int c = 0; c < 20; c++) {
            ar[c] += kp[2 * c] * vg;
            ai[c] += kp[2 * c + 1] * vg;
        }
#pragma unroll
        for (int p = 0; p < 16; p++) {
            ar[20 + p] += pp[2 * p] * v;
            ai[20 + p] += pp[2 * p + 1] * v;
        }
    }
#pragma unroll
    for (int c = 0; c < NCHAN; c++)
        g_S[((b * CCH + j) * NCHAN + c) * DD + d] = make_float2(ar[c], ai[c]);
}

// exclusive prefix over chunks — batched loads/stores for MLP=8
__global__ void prefix_kernel()
{
    int id = blockIdx.x * blockDim.x + threadIdx.x;
    if (id >= BB * NCHAN * DD) return;
    int d = id & (DD - 1);
    int c = (id >> 9) % NCHAN;
    int b = id / (NCHAN * DD);
    float2* base = g_S + (b * CCH * NCHAN + c) * DD + d;
    const int STRIDE = NCHAN * DD;
    float2 run = make_float2(0.f, 0.f);
#pragma unroll
    for (int g = 0; g < 8; g++) {
        float2 buf[8];
#pragma unroll
        for (int k = 0; k < 8; k++) buf[k] = base[(g * 8 + k) * STRIDE];
#pragma unroll
        for (int k = 0; k < 8; k++) {
            float2 t = buf[k];
            buf[k] = run;
            run.x += t.x;
            run.y += t.y;
        }
#pragma unroll
        for (int k = 0; k < 8; k++) base[(g * 8 + k) * STRIDE] = buf[k];
    }
}

// final scan + retrieval + inline gate + LayerNorm
__global__ __launch_bounds__(512) void final_kernel(const float* __restrict__ posw,
                                                    const float* __restrict__ lng,
                                                    const float* __restrict__ lnb,
                                                    const float* __restrict__ g2w,
                                                    const float* __restrict__ g2b)
{
    int j = blockIdx.x, b = blockIdx.y, d = threadIdx.x;
    int l0 = j * SCH;
    __shared__ float skph[SCH * 40];
    __shared__ float sqph[SCH * 40];
    __shared__ float sposp[SCH * 32];
    __shared__ float swg[SCH];
    __shared__ float sgate[SCH];
    __shared__ float sy[SCH][DD];

    for (int i = d; i < SCH * 40; i += 512) {
        skph[i] = g_kph[(b * LL + l0) * 40 + i];
        sqph[i] = g_qph[(b * LL + l0) * 40 + i];
    }
    sposp[d] = g_posph[l0 * 32 + d];
    if (d < SCH) swg[d] = g_wg[b * LL + l0 + d];

    {
        int w = d >> 5, ln = d & 31;
        int grow = (b * CCH + j) * SCH + w;
        float p = 0.f;
#pragma unroll
        for (int k = 0; k < 8; k++) {
            float v = g_hpre[grow * HG + ln + k * 32];
            float ge = 0.5f * v * (1.f + erff(v * 0.70710678118654752f));
            p += ge * g2w[ln + k * 32];
        }
#pragma unroll
        for (int o = 16; o > 0; o >>= 1) p += __shfl_xor_sync(0xffffffffu, p, o);
        if (ln == 0) sgate[w] = 1.f / (1.f + expf(-(p + g2b[0])));
    }
    __syncthreads();

    float spw = 1.f / (1.f + expf(-posw[0]));

    float ar[NCHAN], ai[NCHAN];
#pragma unroll
    for (int c = 0; c < NCHAN; c++) {
        float2 t = g_S[((b * CCH + j) * NCHAN + c) * DD + d];
        ar[c] = t.x;
        ai[c] = t.y;
    }

    for (int l = 0; l < SCH; l++) {
        int lg = l0 + l;
        float v = g_V[(b * LL + lg) * DD + d];
        float vg = v * swg[l];
        const float* kp = skph + l * 40;
        const float* qp = sqph + l * 40;
        const float* pp = sposp + l * 32;
        float r1 = 0.f, r2 = 0.f;
#pragma unroll
        for (int c = 0; c < 20; c++) {
            ar[c] += kp[2 * c] * vg;
            ai[c] += kp[2 * c + 1] * vg;
            r1 += ar[c] * qp[2 * c] + ai[c] * qp[2 * c + 1];
        }
#pragma unroll
        for (int p = 0; p < 16; p++) {
            ar[20 + p] += pp[2 * p] * v;
            ai[20 + p] += pp[2 * p + 1] * v;
            r2 += ar[20 + p] * pp[2 * p] + ai[20 + p] * pp[2 * p + 1];
        }
        float gl = sgate[l];
        sy[l][d] = (gl * r1 + (1.f - gl) * spw * r2) * rsqrtf(4.0f * (float)(lg + 1));
    }
    __syncthreads();

    {
        int w = d >> 5, ln = d & 31;
        float vals[16];
        float s1 = 0.f, s2 = 0.f;
#pragma unroll
        for (int k = 0; k < 16; k++) {
            float t = sy[w][ln + k * 32];
            vals[k] = t;
            s1 += t;
            s2 += t * t;
        }
#pragma unroll
        for (int o = 16; o > 0; o >>= 1) {
            s1 += __shfl_xor_sync(0xffffffffu, s1, o);
            s2 += __shfl_xor_sync(0xffffffffu, s2, o);
        }
        float mu = s1 * (1.f / (float)DD);
        float var = s2 * (1.f / (float)DD) - mu * mu;
        float rstd = rsqrtf(var + 1e-5f);
        int base = (b * LL + l0 + w) * DD;
#pragma unroll
        for (int k = 0; k < 16; k++) {
            int d2 = ln + k * 32;
            float yn = (vals[k] - mu) * rstd * lng[d2] + lnb[d2];
            __nv_bfloat16 h = __float2bfloat16_rn(yn);
            g_ynh[base + d2] = h;
            g_ynl[base + d2] = __float2bfloat16_rn(yn - __bfloat162float(h));
        }
    }
}

// ===================== launch =====================
extern "C" void kernel_launch(void* const* d_in, const int* in_sizes, int n_in,
                              void* d_out, int out_size)
{
    const float* x      = (const float*)d_in[0];
    const float* keyp   = (const float*)d_in[1];
    const float* queryp = (const float*)d_in[2];
    const float* v_w    = (const float*)d_in[4];
    const float* v_b    = (const float*)d_in[5];
    const float* ln_g   = (const float*)d_in[6];
    const float* ln_b   = (const float*)d_in[7];
    const float* out_w  = (const float*)d_in[8];
    const float* out_b  = (const float*)d_in[9];
    const float* setw   = (const float*)d_in[10];
    const float* posf   = (const float*)d_in[11];
    const float* posw   = (const float*)d_in[12];
    const float* g1w    = (const float*)d_in[13];
    const float* g1b    = (const float*)d_in[14];
    const float* g2w    = (const float*)d_in[15];
    const float* g2b    = (const float*)d_in[16];
    const float* sscale = (const float*)d_in[19];
    const float* sbias  = (const float*)d_in[20];
    const float* rscale = (const float*)d_in[21];
    const float* rthr   = (const float*)d_in[22];
    float* out = (float*)d_out;

    cudaFuncSetAttribute(gemm_vh_kernel,
                         cudaFuncAttributeMaxDynamicSharedMemorySize, GM_SMEM_BYTES);
    cudaFuncSetAttribute(gemm_out_kernel,
                         cudaFuncAttributeMaxDynamicSharedMemorySize, GM_SMEM_BYTES);

    // fork s2 off the main (captured) stream
    cudaEventRecord(g_ss.evFork, 0);
    cudaStreamWaitEvent(g_ss.s2, g_ss.evFork, 0);

    // ---- s2: out_w convert (off-path) ----
    convert_og_kernel<<<256, 256, 0, g_ss.s2>>>(out_w);
    cudaEventRecord(g_ss.evOG, g_ss.s2);

    // ---- s0: fused x/vw/g1w converts + phases ----
    convert_phase_kernel<<<1728, 256>>>(x, v_w, g1w, keyp, queryp, setw, posf);

    // ---- s0: merged V + H gemm (192 CTAs, 2 CTA/SM capable) ----
    gemm_vh_kernel<<<dim3(12, RR / 128), 256, GM_SMEM_BYTES>>>(v_b, g1b);

    // ---- s0: scan chain ----
    chunk_sum_kernel<<<dim3(CCH, BB), 512>>>(rscale, rthr, sscale, sbias);
    prefix_kernel<<<(BB * NCHAN * DD + 255) / 256, 256>>>();
    final_kernel<<<dim3(CCH, BB), 512>>>(posw, ln_g, ln_b, g2w, g2b);

    // ---- s0: output projection + residual ----
    cudaStreamWaitEvent(0, g_ss.evOG, 0);
    gemm_out_kernel<<<dim3(DD / 64, RR / 128), 256, GM_SMEM_BYTES>>>(out_b, x, out);
}

// round 17
// speedup vs baseline: 1.1917x; 1.1887x over previous
#include <cuda_runtime.h>
#include <cuda_bf16.h>
#include <math.h>
#include <stdint.h>

// Problem constants
#define BB 2
#define LL 1024
#define DD 512
#define RR (BB * LL)          // 2048 rows
#define TPJ 16                // total planes (NS*PP)
#define PDIM 16               // positional planes
#define NCHAN 36              // 16 bank + 4 cross + 16 positional
#define CCH 64                // chunks along L
#define SCH 16                // chunk size
#define HG 256                // g1 hidden

#define PI_F 3.14159265358979323846f

// ===================== base-ISA tensor helpers =====================
__device__ __forceinline__ uint32_t smem_u32(const void* p) {
    uint32_t a;
    asm("{ .reg .u64 t; cvta.to.shared.u64 t, %1; cvt.u32.u64 %0, t; }" : "=r"(a) : "l"(p));
    return a;
}
__device__ __forceinline__ void ldsm_x4(uint32_t* r, uint32_t addr) {
    asm volatile("ldmatrix.sync.aligned.m8n8.x4.shared.b16 {%0,%1,%2,%3}, [%4];"
                 : "=r"(r[0]), "=r"(r[1]), "=r"(r[2]), "=r"(r[3]) : "r"(addr));
}
__device__ __forceinline__ void mma16816(float* d, const uint32_t* a, const uint32_t* b) {
    asm volatile("mma.sync.aligned.m16n8k16.row.col.f32.bf16.bf16.f32 "
                 "{%0,%1,%2,%3}, {%4,%5,%6,%7}, {%8,%9}, {%0,%1,%2,%3};"
                 : "+f"(d[0]), "+f"(d[1]), "+f"(d[2]), "+f"(d[3])
                 : "r"(a[0]), "r"(a[1]), "r"(a[2]), "r"(a[3]), "r"(b[0]), "r"(b[1]));
}
#define CP_ASYNC16(sm, gp) \
    asm volatile("cp.async.cg.shared.global [%0], [%1], 16;" :: "r"(sm), "l"(gp))
#define CP_COMMIT() asm volatile("cp.async.commit_group;" ::: "memory")
#define CP_WAIT1() asm volatile("cp.async.wait_group 1;" ::: "memory")
#define CP_WAIT0() asm volatile("cp.async.wait_group 0;" ::: "memory")

// ===================== device scratch =====================
__device__ float2 g_S[BB * CCH * NCHAN * DD];
__device__ float  g_V[RR * DD];
__device__ float  g_hpre[RR * HG];
__device__ float  g_gate[RR];
__device__ float  g_wg[RR];
__device__ float  g_kph[RR * 40];
__device__ float  g_qph[RR * 40];
__device__ float  g_posph[LL * 32];
__device__ __nv_bfloat16 g_xh[RR * DD], g_xl[RR * DD];
__device__ __nv_bfloat16 g_ynh[RR * DD], g_ynl[RR * DD];
__device__ __nv_bfloat16 g_wvh[DD * DD], g_wvl[DD * DD];
__device__ __nv_bfloat16 g_woh[DD * DD], g_wol[DD * DD];
__device__ __nv_bfloat16 g_wgh[HG * DD], g_wgl[HG * DD];

// ===================== side-stream infra (static init: pre-checkpoint) =====
__global__ void warm_kernel() {}
struct SideStreams {
    cudaStream_t s1, s2;
    cudaEvent_t evFork, evConv, evB, evGate;
    SideStreams() {
        cudaStreamCreateWithFlags(&s1, cudaStreamNonBlocking);
        cudaStreamCreateWithFlags(&s2, cudaStreamNonBlocking);
        cudaEventCreateWithFlags(&evFork, cudaEventDisableTiming);
        cudaEventCreateWithFlags(&evConv, cudaEventDisableTiming);
        cudaEventCreateWithFlags(&evB, cudaEventDisableTiming);
        cudaEventCreateWithFlags(&evGate, cudaEventDisableTiming);
        warm_kernel<<<1, 32, 0, s1>>>();
        warm_kernel<<<1, 32, 0, s2>>>();
        cudaDeviceSynchronize();
    }
};
static SideStreams g_ss;

// ===================== fused conversions (x + all weights, one launch) =====
__global__ __launch_bounds__(256) void convert_all_kernel(
    const float* __restrict__ x, const float* __restrict__ vw,
    const float* __restrict__ g1w, const float* __restrict__ ow)
{
    __shared__ float t[32][33];
    int bx = blockIdx.x, tid = threadIdx.x;
    if (bx < 1024) {
        int i = bx * 256 + tid;
        float4 v = ((const float4*)x)[i];
        float f[4] = {v.x, v.y, v.z, v.w};
        __nv_bfloat16 h[4], l[4];
#pragma unroll
        for (int k = 0; k < 4; k++) {
            h[k] = __float2bfloat16_rn(f[k]);
            l[k] = __float2bfloat16_rn(f[k] - __bfloat162float(h[k]));
        }
        ((__nv_bfloat162*)g_xh)[2 * i]     = __nv_bfloat162(h[0], h[1]);
        ((__nv_bfloat162*)g_xh)[2 * i + 1] = __nv_bfloat162(h[2], h[3]);
        ((__nv_bfloat162*)g_xl)[2 * i]     = __nv_bfloat162(l[0], l[1]);
        ((__nv_bfloat162*)g_xl)[2 * i + 1] = __nv_bfloat162(l[2], l[3]);
        return;
    }
    int wb = bx - 1024;                 // 0..767
    int z = wb >> 8, rem = wb & 255;
    const float* W;
    __nv_bfloat16 *Th, *Tl;
    int N;
    if (z == 0)      { W = vw;  Th = g_wvh; Tl = g_wvl; N = DD; }
    else if (z == 1) { W = ow;  Th = g_woh; Tl = g_wol; N = DD; }
    else             { W = g1w; Th = g_wgh; Tl = g_wgl; N = HG; }
    int n0 = (rem & 15) * 32, k0 = (rem >> 4) * 32;
    if (n0 >= N) return;
    int tx = tid & 31, ty = tid >> 5;   // 32 x 8
#pragma unroll
    for (int i = 0; i < 32; i += 8) t[ty + i][tx] = W[(k0 + ty + i) * N + n0 + tx];
    __syncthreads();
#pragma unroll
    for (int i = 0; i < 32; i += 8) {
        float v = t[tx][ty + i];
        __nv_bfloat16 h = __float2bfloat16_rn(v);
        Th[(n0 + ty + i) * DD + k0 + tx] = h;
        Tl[(n0 + ty + i) * DD + k0 + tx] = __float2bfloat16_rn(v - __bfloat162float(h));
    }
}

// ===================== mma.sync GEMM (bf16 hi/lo split) =====================
#define ST_EL 15360
#define GM_SMEM_BYTES (2 * ST_EL * 2)

template <bool RESID>
__global__ void __launch_bounds__(256) gemm_mma_kernel(
    const __nv_bfloat16* __restrict__ Ah, const __nv_bfloat16* __restrict__ Al,
    const __nv_bfloat16* __restrict__ Bh, const __nv_bfloat16* __restrict__ Bl,
    const float* __restrict__ bias, const float* __restrict__ resid,
    float* __restrict__ C, int Ntot)
{
    extern __shared__ __nv_bfloat16 smem[];
    const int tid = threadIdx.x, lane = tid & 31, wid = tid >> 5;
    const int wm = (wid >> 1) * 32, wn = (wid & 1) * 32;
    const int bm = blockIdx.y * 128, bn = blockIdx.x * 64;
    const int K = 512;

    uint32_t sbase = smem_u32(smem);
    int arow = tid >> 2, aq = tid & 3;
    int brow = tid >> 2, bq = tid & 3;

    auto load_chunk = [&](int c, int s) {
        uint32_t st = sbase + s * ST_EL * 2;
        int k0 = c * 32;
#pragma unroll
        for (int i = 0; i < 2; i++) {
            int r = arow + i * 64;
            uint32_t so = st + (r * 40 + aq * 8) * 2;
            CP_ASYNC16(so, Ah + (bm + r) * K + k0 + aq * 8);
            CP_ASYNC16(so + 5120 * 2, Al + (bm + r) * K + k0 + aq * 8);
        }
        {
            uint32_t so = st + (10240 + brow * 40 + bq * 8) * 2;
            CP_ASYNC16(so, Bh + (bn + brow) * K + k0 + bq * 8);
            CP_ASYNC16(so + 2560 * 2, Bl + (bn + brow) * K + k0 + bq * 8);
        }
    };

    float acc[2][4][4];
#pragma unroll
    for (int mt = 0; mt < 2; mt++)
#pragma unroll
        for (int nt = 0; nt < 4; nt++)
#pragma unroll
            for (int e = 0; e < 4; e++) acc[mt][nt][e] = 0.f;

    load_chunk(0, 0);
    CP_COMMIT();

    int a_row = (lane & 7) + ((lane >> 3) & 1) * 8;
    int a_k16 = ((lane >> 4) & 1) * 16;
    int b_row = (lane & 7) + ((lane >> 4) & 1) * 8;
    int b_k16 = ((lane >> 3) & 1) * 16;

    for (int c = 0; c < 16; c++) {
        int s = c & 1;
        if (c + 1 < 16) { load_chunk(c + 1, s ^ 1); CP_COMMIT(); CP_WAIT1(); }
        else CP_WAIT0();
        __syncthreads();

        uint32_t st = sbase + s * ST_EL * 2;
#pragma unroll
        for (int ks = 0; ks < 2; ks++) {
            uint32_t aH[8], aL[8], bH[8], bL[8];
#pragma unroll
            for (int mt = 0; mt < 2; mt++) {
                int row = wm + mt * 16 + a_row;
                uint32_t ad = st + (row * 40) * 2 + ks * 32 + a_k16;
                ldsm_x4(aH + mt * 4, ad);
                ldsm_x4(aL + mt * 4, ad + 5120 * 2);
            }
#pragma unroll
            for (int np = 0; np < 2; np++) {
                int row = wn + np * 16 + b_row;
                uint32_t bd = st + (10240 + row * 40) * 2 + ks * 32 + b_k16;
                ldsm_x4(bH + np * 4, bd);
                ldsm_x4(bL + np * 4, bd + 2560 * 2);
            }
#pragma unroll
            for (int mt = 0; mt < 2; mt++)
#pragma unroll
                for (int nt = 0; nt < 4; nt++) {
                    uint32_t* bh = bH + (nt >> 1) * 4 + (nt & 1) * 2;
                    uint32_t* bl = bL + (nt >> 1) * 4 + (nt & 1) * 2;
                    mma16816(acc[mt][nt], aH + mt * 4, bh);
                    mma16816(acc[mt][nt], aH + mt * 4, bl);
                    mma16816(acc[mt][nt], aL + mt * 4, bh);
                }
        }
        __syncthreads();
    }

#pragma unroll
    for (int mt = 0; mt < 2; mt++)
#pragma unroll
        for (int nt = 0; nt < 4; nt++) {
            int col = bn + wn + nt * 8 + (lane & 3) * 2;
            float b0 = bias[col], b1 = bias[col + 1];
#pragma unroll
            for (int h = 0; h < 2; h++) {
                int row = bm + wm + mt * 16 + (lane >> 2) + h * 8;
                float2 o;
                o.x = acc[mt][nt][h * 2 + 0] + b0;
                o.y = acc[mt][nt][h * 2 + 1] + b1;
                if (RESID) {
                    float2 rr = *(const float2*)&resid[row * Ntot + col];
                    o.x += rr.x; o.y += rr.y;
                }
                *(float2*)&C[row * Ntot + col] = o;
            }
        }
}

// ===================== phase kernel (proj phases + positional phases) =====
__global__ __launch_bounds__(256) void phase_kernel(
    const float* __restrict__ x, const float* __restrict__ keyp,
    const float* __restrict__ queryp, const float* __restrict__ setw,
    const float* __restrict__ freqs)
{
    if (blockIdx.x >= 256) {
        int i = (blockIdx.x - 256) * 256 + threadIdx.x;
        int l = i >> 4, p = i & 15;
        float a = ((float)l * freqs[p]) * (2.0f * PI_F);
        float s, c;
        sincosf(a, &s, &c);
        g_posph[l * 32 + 2 * p] = c;
        g_posph[l * 32 + 2 * p + 1] = s;
        return;
    }
    int row = blockIdx.x * 8 + (threadIdx.x >> 5);
    int lane = threadIdx.x & 31;
    int t = lane & 15;
    const float* W = (lane < 16) ? keyp : queryp;
    const float* xr = x + row * DD;
    float acc = 0.f;
    for (int k = 0; k < DD; k++) acc += xr[k] * W[k * TPJ + t];
    float theta = tanhf(acc) * PI_F;

    float csum = theta;
    csum += __shfl_xor_sync(0xffffffffu, csum, 4);
    csum += __shfl_xor_sync(0xffffffffu, csum, 8);

    float w0 = setw[0], w1 = setw[1], w2 = setw[2], w3 = setw[3];
    float m = fmaxf(fmaxf(w0, w1), fmaxf(w2, w3));
    float e0 = expf(w0 - m), e1 = expf(w1 - m), e2 = expf(w2 - m), e3 = expf(w3 - m);
    float inv = 1.f / (e0 + e1 + e2 + e3);
    float wv[4] = {e0 * inv, e1 * inv, e2 * inv, e3 * inv};

    float s, c;
    sincosf(theta, &s, &c);
    if (lane < 16) {
        g_kph[row * 40 + 2 * t] = c;
        g_kph[row * 40 + 2 * t + 1] = s;
        if (t < 4) {
            float s2, c2;
            sincosf(csum, &s2, &c2);
            g_kph[row * 40 + 2 * (16 + t)] = c2;
            g_kph[row * 40 + 2 * (16 + t) + 1] = s2;
        }
    } else {
        float wq = wv[t >> 2] * 0.2f;
        g_qph[row * 40 + 2 * t] = c * wq;
        g_qph[row * 40 + 2 * t + 1] = s * wq;
        if (t < 4) {
            float s2, c2;
            sincosf(csum, &s2, &c2);
            g_qph[row * 40 + 2 * (16 + t)] = c2 * 0.2f;
            g_qph[row * 40 + 2 * (16 + t) + 1] = s2 * 0.2f;
        }
    }
}

__global__ __launch_bounds__(1024) void wg_scan_kernel(
    const float* __restrict__ rscale, const float* __restrict__ rthr,
    const float* __restrict__ sscale, const float* __restrict__ sbias)
{
    int b = blockIdx.x;
    int l = threadIdx.x;
    int lane = l & 31, wp = l >> 5;

    float v[8], own[8];
    const float* src = g_kph + (b * LL + l) * 40 + 32;
#pragma unroll
    for (int c = 0; c < 8; c++) { v[c] = src[c]; own[c] = v[c]; }
#pragma unroll
    for (int off = 1; off < 32; off <<= 1) {
#pragma unroll
        for (int c = 0; c < 8; c++) {
            float t = __shfl_up_sync(0xffffffffu, v[c], off);
            if (lane >= off) v[c] += t;
        }
    }
    __shared__ float wtot[32][8];
    if (lane == 31) {
#pragma unroll
        for (int c = 0; c < 8; c++) wtot[wp][c] = v[c];
    }
    __syncthreads();
    if (wp == 0) {
        float w[8];
#pragma unroll
        for (int c = 0; c < 8; c++) w[c] = wtot[lane][c];
#pragma unroll
        for (int off = 1; off < 32; off <<= 1) {
#pragma unroll
            for (int c = 0; c < 8; c++) {
                float t = __shfl_up_sync(0xffffffffu, w[c], off);
                if (lane >= off) w[c] += t;
            }
        }
#pragma unroll
        for (int c = 0; c < 8; c++) wtot[lane][c] = w[c];
    }
    __syncthreads();

    float mag = 0.f;
#pragma unroll
    for (int p = 0; p < 4; p++) {
        float woc = (wp > 0) ? wtot[wp - 1][2 * p] : 0.f;
        float wos = (wp > 0) ? wtot[wp - 1][2 * p + 1] : 0.f;
        float cr = woc + v[2 * p] - own[2 * p];
        float ci = wos + v[2 * p + 1] - own[2 * p + 1];
        mag += sqrtf(cr * cr + ci * ci);
    }
    mag *= 0.25f;

    float rs = fminf(fmaxf(rscale[0], 1.f), 20.f);
    float th = fminf(fmaxf(rthr[0], 0.1f), 0.9f);
    float nres = mag * rsqrtf(fmaxf((float)l, 1.f));
    float sup = 0.5f * (1.f - tanhf(rs * (nres - th)));
    g_wg[b * LL + l] = 1.f / (1.f + expf(-(sscale[0] * (sup - 0.5f) + sbias[0])));
}

__global__ __launch_bounds__(256) void gate_kernel(const float* __restrict__ g2w,
                                                   const float* __restrict__ g2b)
{
    int row = blockIdx.x;
    int tid = threadIdx.x;
    float v = g_hpre[row * HG + tid];
    float ge = 0.5f * v * (1.f + erff(v * 0.70710678118654752f));
    float p = ge * g2w[tid];
#pragma unroll
    for (int o = 16; o > 0; o >>= 1) p += __shfl_down_sync(0xffffffffu, p, o);
    __shared__ float red[8];
    if ((tid & 31) == 0) red[tid >> 5] = p;
    __syncthreads();
    if (tid == 0) {
        float s = red[0] + red[1] + red[2] + red[3] + red[4] + red[5] + red[6] + red[7];
        g_gate[row] = 1.f / (1.f + expf(-(s + g2b[0])));
    }
}

__global__ __launch_bounds__(512) void chunk_sum_kernel()
{
    int j = blockIdx.x, b = blockIdx.y, d = threadIdx.x;
    int l0 = j * SCH;
    __shared__ float skph[SCH * 40];
    __shared__ float sposp[SCH * 32];
    __shared__ float swg[SCH];
    for (int i = d; i < SCH * 40; i += DD) skph[i] = g_kph[(b * LL + l0) * 40 + i];
    for (int i = d; i < SCH * 32; i += DD) sposp[i] = g_posph[l0 * 32 + i];
    if (d < SCH) swg[d] = g_wg[b * LL + l0 + d];
    __syncthreads();

    float ar[NCHAN], ai[NCHAN];
#pragma unroll
    for (int c = 0; c < NCHAN; c++) { ar[c] = 0.f; ai[c] = 0.f; }

    for (int l = 0; l < SCH; l++) {
        float v = g_V[(b * LL + l0 + l) * DD + d];
        float vg = v * swg[l];
        const float* kp = skph + l * 40;
        const float* pp = sposp + l * 32;
#pragma unroll
        for (int c = 0; c < 20; c++) {
            ar[c] += kp[2 * c] * vg;
            ai[c] += kp[2 * c + 1] * vg;
        }
#pragma unroll
        for (int p = 0; p < 16; p++) {
            ar[20 + p] += pp[2 * p] * v;
            ai[20 + p] += pp[2 * p + 1] * v;
        }
    }
#pragma unroll
    for (int c = 0; c < NCHAN; c++)
        g_S[((b * CCH + j) * NCHAN + c) * DD + d] = make_float2(ar[c], ai[c]);
}

// exclusive prefix over chunks — batched loads/stores for MLP=8
__global__ void prefix_kernel()
{
    int id = blockIdx.x * blockDim.x + threadIdx.x;
    if (id >= BB * NCHAN * DD) return;
    int d = id & (DD - 1);
    int c = (id >> 9) % NCHAN;
    int b = id / (NCHAN * DD);
    float2* base = g_S + (b * CCH * NCHAN + c) * DD + d;
    const int STRIDE = NCHAN * DD;
    float2 run = make_float2(0.f, 0.f);
#pragma unroll
    for (int g = 0; g < 8; g++) {
        float2 buf[8];
#pragma unroll
        for (int k = 0; k < 8; k++) buf[k] = base[(g * 8 + k) * STRIDE];
#pragma unroll
        for (int k = 0; k < 8; k++) {
            float2 t = buf[k];
            buf[k] = run;
            run.x += t.x;
            run.y += t.y;
        }
#pragma unroll
        for (int k = 0; k < 8; k++) base[(g * 8 + k) * STRIDE] = buf[k];
    }
}

// final scan + retrieval + LayerNorm (gate precomputed in g_gate)
__global__ __launch_bounds__(512) void final_kernel(const float* __restrict__ posw,
                                                    const float* __restrict__ lng,
                                                    const float* __restrict__ lnb)
{
    int j = blockIdx.x, b = blockIdx.y, d = threadIdx.x;
    int l0 = j * SCH;
    __shared__ float skph[SCH * 40];
    __shared__ float sqph[SCH * 40];
    __shared__ float sposp[SCH * 32];
    __shared__ float swg[SCH];
    __shared__ float sgate[SCH];
    __shared__ float sy[SCH][DD];

    for (int i = d; i < SCH * 40; i += 512) {
        skph[i] = g_kph[(b * LL + l0) * 40 + i];
        sqph[i] = g_qph[(b * LL + l0) * 40 + i];
    }
    sposp[d] = g_posph[l0 * 32 + d];
    if (d < SCH) {
        swg[d] = g_wg[b * LL + l0 + d];
        sgate[d] = g_gate[b * LL + l0 + d];
    }
    __syncthreads();

    float spw = 1.f / (1.f + expf(-posw[0]));

    float ar[NCHAN], ai[NCHAN];
#pragma unroll
    for (int c = 0; c < NCHAN; c++) {
        float2 t = g_S[((b * CCH + j) * NCHAN + c) * DD + d];
        ar[c] = t.x;
        ai[c] = t.y;
    }

    for (int l = 0; l < SCH; l++) {
        int lg = l0 + l;
        float v = g_V[(b * LL + lg) * DD + d];
        float vg = v * swg[l];
        const float* kp = skph + l * 40;
        const float* qp = sqph + l * 40;
        const float* pp = sposp + l * 32;
        float r1 = 0.f, r2 = 0.f;
#pragma unroll
        for (int c = 0; c < 20; c++) {
            ar[c] += kp[2 * c] * vg;
            ai[c] += kp[2 * c + 1] * vg;
            r1 += ar[c] * qp[2 * c] + ai[c] * qp[2 * c + 1];
        }
#pragma unroll
        for (int p = 0; p < 16; p++) {
            ar[20 + p] += pp[2 * p] * v;
            ai[20 + p] += pp[2 * p + 1] * v;
            r2 += ar[20 + p] * pp[2 * p] + ai[20 + p] * pp[2 * p + 1];
        }
        float gl = sgate[l];
        sy[l][d] = (gl * r1 + (1.f - gl) * spw * r2) * rsqrtf(4.0f * (float)(lg + 1));
    }
    __syncthreads();

    // LayerNorm: one warp per row (16 warps, 16 rows)
    {
        int w = d >> 5, ln = d & 31;
        float vals[16];
        float s1 = 0.f, s2 = 0.f;
#pragma unroll
        for (int k = 0; k < 16; k++) {
            float t = sy[w][ln + k * 32];
            vals[k] = t;
            s1 += t;
            s2 += t * t;
        }
#pragma unroll
        for (int o = 16; o > 0; o >>= 1) {
            s1 += __shfl_xor_sync(0xffffffffu, s1, o);
            s2 += __shfl_xor_sync(0xffffffffu, s2, o);
        }
        float mu = s1 * (1.f / (float)DD);
        float var = s2 * (1.f / (float)DD) - mu * mu;
        float rstd = rsqrtf(var + 1e-5f);
        int base = (b * LL + l0 + w) * DD;
#pragma unroll
        for (int k = 0; k < 16; k++) {
            int d2 = ln + k * 32;
            float yn = (vals[k] - mu) * rstd * lng[d2] + lnb[d2];
            __nv_bfloat16 h = __float2bfloat16_rn(yn);
            g_ynh[base + d2] = h;
            g_ynl[base + d2] = __float2bfloat16_rn(yn - __bfloat162float(h));
        }
    }
}

// ===================== launch =====================
extern "C" void kernel_launch(void* const* d_in, const int* in_sizes, int n_in,
                              void* d_out, int out_size)
{
    const float* x      = (const float*)d_in[0];
    const float* keyp   = (const float*)d_in[1];
    const float* queryp = (const float*)d_in[2];
    const float* v_w    = (const float*)d_in[4];
    const float* v_b    = (const float*)d_in[5];
    const float* ln_g   = (const float*)d_in[6];
    const float* ln_b   = (const float*)d_in[7];
    const float* out_w  = (const float*)d_in[8];
    const float* out_b  = (const float*)d_in[9];
    const float* setw   = (const float*)d_in[10];
    const float* posf   = (const float*)d_in[11];
    const float* posw   = (const float*)d_in[12];
    const float* g1w    = (const float*)d_in[13];
    const float* g1b    = (const float*)d_in[14];
    const float* g2w    = (const float*)d_in[15];
    const float* g2b    = (const float*)d_in[16];
    const float* sscale = (const float*)d_in[19];
    const float* sbias  = (const float*)d_in[20];
    const float* rscale = (const float*)d_in[21];
    const float* rthr   = (const float*)d_in[22];
    float* out = (float*)d_out;

    cudaFuncSetAttribute(gemm_mma_kernel<false>,
                         cudaFuncAttributeMaxDynamicSharedMemorySize, GM_SMEM_BYTES);
    cudaFuncSetAttribute(gemm_mma_kernel<true>,
                         cudaFuncAttributeMaxDynamicSharedMemorySize, GM_SMEM_BYTES);

    float *pV, *pH;
    __nv_bfloat16 *pXh, *pXl, *pYh, *pYl, *pWvh, *pWvl, *pWoh, *pWol, *pWgh, *pWgl;
    cudaGetSymbolAddress((void**)&pV, g_V);
    cudaGetSymbolAddress((void**)&pH, g_hpre);
    cudaGetSymbolAddress((void**)&pXh, g_xh);
    cudaGetSymbolAddress((void**)&pXl, g_xl);
    cudaGetSymbolAddress((void**)&pYh, g_ynh);
    cudaGetSymbolAddress((void**)&pYl, g_ynl);
    cudaGetSymbolAddress((void**)&pWvh, g_wvh);
    cudaGetSymbolAddress((void**)&pWvl, g_wvl);
    cudaGetSymbolAddress((void**)&pWoh, g_woh);
    cudaGetSymbolAddress((void**)&pWol, g_wol);
    cudaGetSymbolAddress((void**)&pWgh, g_wgh);
    cudaGetSymbolAddress((void**)&pWgl, g_wgl);

    // fork side streams off the main (captured) stream
    cudaEventRecord(g_ss.evFork, 0);
    cudaStreamWaitEvent(g_ss.s1, g_ss.evFork, 0);

    // ---- chain B (s1): phases + write gate ----
    phase_kernel<<<320, 256, 0, g_ss.s1>>>(x, keyp, queryp, setw, posf);
    wg_scan_kernel<<<BB, LL, 0, g_ss.s1>>>(rscale, rthr, sscale, sbias);
    cudaEventRecord(g_ss.evB, g_ss.s1);

    // ---- chain A (s0): converts + V gemm ----
    convert_all_kernel<<<1792, 256>>>(x, v_w, g1w, out_w);
    cudaEventRecord(g_ss.evConv, 0);
    cudaStreamWaitEvent(g_ss.s2, g_ss.evConv, 0);

    gemm_mma_kernel<false><<<dim3(DD / 64, RR / 128), 256, GM_SMEM_BYTES>>>(
        pXh, pXl, pWvh, pWvl, v_b, nullptr, pV, DD);

    // ---- chain C (s2): H gemm + gate ----
    gemm_mma_kernel<false><<<dim3(HG / 64, RR / 128), 256, GM_SMEM_BYTES, g_ss.s2>>>(
        pXh, pXl, pWgh, pWgl, g1b, nullptr, pH, HG);
    gate_kernel<<<RR, HG, 0, g_ss.s2>>>(g2w, g2b);
    cudaEventRecord(g_ss.evGate, g_ss.s2);

    // ---- join + scan chain on s0 ----
    cudaStreamWaitEvent(0, g_ss.evB, 0);
    chunk_sum_kernel<<<dim3(CCH, BB), DD>>>();
    prefix_kernel<<<(BB * NCHAN * DD + 255) / 256, 256>>>();
    cudaStreamWaitEvent(0, g_ss.evGate, 0);
    final_kernel<<<dim3(CCH, BB), DD>>>(posw, ln_g, ln_b);

    // output projection + residual
    gemm_mma_kernel<true><<<dim3(DD / 64, RR / 128), 256, GM_SMEM_BYTES>>>(
        pYh, pYl, pWoh, pWol, out_b, x, out, DD);
}